// round 9
// baseline (speedup 1.0000x reference)
#include <cuda_runtime.h>
#include <math.h>
#include <stdint.h>

// ---------------- problem constants ----------------
#define Bc   32
#define NRc  4096
#define DIN  384
#define DCTX 128
#define Hc   64
#define Ac   16
#define MTOT (Bc * NRc)

#define LOG_VAR2_C  (-4.6051701859880914f)
#define INV_VAR2_C  (100.0f)
#define STD2_C      (0.1f)

// ---------------- device scratch ----------------
__device__ float g_embT[(size_t)Bc * Hc * NRc];   // [b][k][n]
__device__ float g_h[(size_t)MTOT * Hc];          // h = relu(roles@W1+b1)
__device__ float g_mse[Bc];
__device__ float g_kld[Bc];

// ---------------- zero accumulators ----------------
__global__ void zero_kernel() {
    int t = threadIdx.x;
    if (t < Bc) { g_mse[t] = 0.0f; g_kld[t] = 0.0f; }
}

// ---------------- tf32 / mma helpers ----------------
__device__ __forceinline__ float tf32r(float x) {
    uint32_t u; asm("cvt.rna.tf32.f32 %0, %1;" : "=r"(u) : "f"(x));
    return __uint_as_float(u);
}
__device__ __forceinline__ void mma_tf32(float c[4], const uint32_t a[4],
                                         uint32_t b0, uint32_t b1) {
    asm volatile("mma.sync.aligned.m16n8k8.row.col.f32.tf32.tf32.f32 "
        "{%0,%1,%2,%3}, {%4,%5,%6,%7}, {%8,%9}, {%0,%1,%2,%3};"
        : "+f"(c[0]), "+f"(c[1]), "+f"(c[2]), "+f"(c[3])
        : "r"(a[0]), "r"(a[1]), "r"(a[2]), "r"(a[3]), "r"(b0), "r"(b1));
}

#define WSP 68   // conflict-free row stride (floats)

// ---------------- hybrid GEMM1: h = relu(roles @ W1 + b1) ----------------------
// 1024 blocks x 256 thr. Warps 0-3: rows 0-63 exact scalar fp32 (FMA pipe).
// Warps 4-7: rows 64-127 via 3xTF32 HMMA (tensor pipe). Both run concurrently.
// smem floats: As[64*WSP] Bs[64*WSP] AH[64*WSP] AL[64*WSP] WH[64*WSP] WL[64*WSP]
#define G1_SMEM_FLOATS (6*64*WSP)

__global__ __launch_bounds__(256, 2)
void gemm1_kernel(const float* __restrict__ roles, const float* __restrict__ W1,
                  const float* __restrict__ b1)
{
    extern __shared__ float sg[];
    float* As = sg;               // scalar A tile [k][m] rows 0-63
    float* Bs = As + 64*WSP;      // scalar W tile [k][n]
    float* AH = Bs + 64*WSP;      // tensor A hi  [r][k] rows 64-127
    float* AL = AH + 64*WSP;      // tensor A lo
    float* WH = AL + 64*WSP;      // tensor W hi (permuted)
    float* WL = WH + 64*WSP;      // tensor W lo (permuted)

    const int tid  = threadIdx.x;
    const int wid  = tid >> 5;
    const int lane = tid & 31;
    const int row0 = blockIdx.x * 128;

    // scalar thread mapping (warps 0-3, 128 threads, 64 rows)
    const int tcol = tid & 15;              // 16 col groups x 4
    const int trow = (tid >> 4) & 7;        // 8 row groups x 8
    // tensor thread mapping (warps 4-7)
    const int gid  = lane >> 2;
    const int tig  = lane & 3;
    const int mrow = (wid - 4) * 16;        // local row within [64,128)

    float acc[8][4];                        // scalar accumulators
    float cfr[8][4];                        // tensor accumulators
#pragma unroll
    for (int i = 0; i < 8; i++)
#pragma unroll
        for (int j = 0; j < 4; j++) { acc[i][j] = 0.0f; cfr[i][j] = 0.0f; }

    for (int t = 0; t < 6; t++) {
        const int kt0 = t * 64;
        __syncthreads();   // previous tile reads complete

        // ---- stage scalar A rows 0-63: As[k][m], fp32
        for (int f = tid; f < 1024; f += 256) {
            int m  = f >> 4;
            int k4 = (f & 15) << 2;
            float4 v = *reinterpret_cast<const float4*>(
                roles + (size_t)(row0 + m) * DIN + kt0 + k4);
            As[(k4 + 0) * WSP + m] = v.x;
            As[(k4 + 1) * WSP + m] = v.y;
            As[(k4 + 2) * WSP + m] = v.z;
            As[(k4 + 3) * WSP + m] = v.w;
        }
        // ---- stage tensor A rows 64-127: AH/AL[r][k] hi/lo
        for (int f = tid; f < 1024; f += 256) {
            int r  = f >> 4;
            int c4 = (f & 15) << 2;
            float4 v = *reinterpret_cast<const float4*>(
                roles + (size_t)(row0 + 64 + r) * DIN + kt0 + c4);
            float hx = tf32r(v.x), hy = tf32r(v.y), hz = tf32r(v.z), hw = tf32r(v.w);
            *reinterpret_cast<float4*>(&AH[r*WSP + c4]) = make_float4(hx, hy, hz, hw);
            *reinterpret_cast<float4*>(&AL[r*WSP + c4]) =
                make_float4(tf32r(v.x - hx), tf32r(v.y - hy),
                            tf32r(v.z - hz), tf32r(v.w - hw));
        }
        // ---- stage scalar W tile: Bs[k][n] fp32
        for (int f = tid; f < 1024; f += 256) {
            int k  = f >> 4;
            int n4 = (f & 15) << 2;
            *reinterpret_cast<float4*>(&Bs[k*WSP + n4]) =
                *reinterpret_cast<const float4*>(W1 + (size_t)(kt0 + k) * Hc + n4);
        }
        // ---- stage tensor W tile hi/lo, permuted vector layout
        for (int f = tid; f < 4096; f += 256) {
            int k = f >> 6, n = f & 63;
            float x = W1[(size_t)(kt0 + k) * Hc + n];
            float hx = tf32r(x);
            int pos = k*WSP + ((n & 7) << 3) + (n >> 3);
            WH[pos] = hx;
            WL[pos] = tf32r(x - hx);
        }
        __syncthreads();

        if (wid < 4) {
            // ================= scalar fp32 path (rows 0-63) =================
#pragma unroll 8
            for (int k = 0; k < 64; k++) {
                float a[8];
                *reinterpret_cast<float4*>(&a[0]) =
                    *reinterpret_cast<float4*>(&As[k*WSP + trow*8]);
                *reinterpret_cast<float4*>(&a[4]) =
                    *reinterpret_cast<float4*>(&As[k*WSP + trow*8 + 4]);
                float4 bb = *reinterpret_cast<float4*>(&Bs[k*WSP + tcol*4]);
#pragma unroll
                for (int i = 0; i < 8; i++) {
                    acc[i][0] += a[i] * bb.x;
                    acc[i][1] += a[i] * bb.y;
                    acc[i][2] += a[i] * bb.z;
                    acc[i][3] += a[i] * bb.w;
                }
            }
        } else {
            // ================= 3xTF32 HMMA path (rows 64-127) =================
#pragma unroll
            for (int kt = 0; kt < 8; kt++) {
                int k0 = kt * 8;
                uint32_t ah[4], al[4];
                ah[0] = __float_as_uint(AH[(mrow+gid  )*WSP + k0+tig  ]);
                ah[1] = __float_as_uint(AH[(mrow+gid+8)*WSP + k0+tig  ]);
                ah[2] = __float_as_uint(AH[(mrow+gid  )*WSP + k0+tig+4]);
                ah[3] = __float_as_uint(AH[(mrow+gid+8)*WSP + k0+tig+4]);
                al[0] = __float_as_uint(AL[(mrow+gid  )*WSP + k0+tig  ]);
                al[1] = __float_as_uint(AL[(mrow+gid+8)*WSP + k0+tig  ]);
                al[2] = __float_as_uint(AL[(mrow+gid  )*WSP + k0+tig+4]);
                al[3] = __float_as_uint(AL[(mrow+gid+8)*WSP + k0+tig+4]);
                const float4* ph0 = reinterpret_cast<const float4*>(&WH[(k0+tig  )*WSP + gid*8]);
                const float4* ph1 = reinterpret_cast<const float4*>(&WH[(k0+tig+4)*WSP + gid*8]);
                const float4* pl0 = reinterpret_cast<const float4*>(&WL[(k0+tig  )*WSP + gid*8]);
                const float4* pl1 = reinterpret_cast<const float4*>(&WL[(k0+tig+4)*WSP + gid*8]);
                float4 h0a = ph0[0], h0b = ph0[1], h1a = ph1[0], h1b = ph1[1];
                float4 l0a = pl0[0], l0b = pl0[1], l1a = pl1[0], l1b = pl1[1];
                // Ah*Wh
                mma_tf32(cfr[0], ah, __float_as_uint(h0a.x), __float_as_uint(h1a.x));
                mma_tf32(cfr[1], ah, __float_as_uint(h0a.y), __float_as_uint(h1a.y));
                mma_tf32(cfr[2], ah, __float_as_uint(h0a.z), __float_as_uint(h1a.z));
                mma_tf32(cfr[3], ah, __float_as_uint(h0a.w), __float_as_uint(h1a.w));
                mma_tf32(cfr[4], ah, __float_as_uint(h0b.x), __float_as_uint(h1b.x));
                mma_tf32(cfr[5], ah, __float_as_uint(h0b.y), __float_as_uint(h1b.y));
                mma_tf32(cfr[6], ah, __float_as_uint(h0b.z), __float_as_uint(h1b.z));
                mma_tf32(cfr[7], ah, __float_as_uint(h0b.w), __float_as_uint(h1b.w));
                // Ah*Wl
                mma_tf32(cfr[0], ah, __float_as_uint(l0a.x), __float_as_uint(l1a.x));
                mma_tf32(cfr[1], ah, __float_as_uint(l0a.y), __float_as_uint(l1a.y));
                mma_tf32(cfr[2], ah, __float_as_uint(l0a.z), __float_as_uint(l1a.z));
                mma_tf32(cfr[3], ah, __float_as_uint(l0a.w), __float_as_uint(l1a.w));
                mma_tf32(cfr[4], ah, __float_as_uint(l0b.x), __float_as_uint(l1b.x));
                mma_tf32(cfr[5], ah, __float_as_uint(l0b.y), __float_as_uint(l1b.y));
                mma_tf32(cfr[6], ah, __float_as_uint(l0b.z), __float_as_uint(l1b.z));
                mma_tf32(cfr[7], ah, __float_as_uint(l0b.w), __float_as_uint(l1b.w));
                // Al*Wh
                mma_tf32(cfr[0], al, __float_as_uint(h0a.x), __float_as_uint(h1a.x));
                mma_tf32(cfr[1], al, __float_as_uint(h0a.y), __float_as_uint(h1a.y));
                mma_tf32(cfr[2], al, __float_as_uint(h0a.z), __float_as_uint(h1a.z));
                mma_tf32(cfr[3], al, __float_as_uint(h0a.w), __float_as_uint(h1a.w));
                mma_tf32(cfr[4], al, __float_as_uint(h0b.x), __float_as_uint(h1b.x));
                mma_tf32(cfr[5], al, __float_as_uint(h0b.y), __float_as_uint(h1b.y));
                mma_tf32(cfr[6], al, __float_as_uint(h0b.z), __float_as_uint(h1b.z));
                mma_tf32(cfr[7], al, __float_as_uint(h0b.w), __float_as_uint(h1b.w));
            }
        }
    }

    // ---- epilogue: relu(+b1) -> g_h
    if (wid < 4) {
        float4 bv = *reinterpret_cast<const float4*>(b1 + tcol * 4);
#pragma unroll
        for (int i = 0; i < 8; i++) {
            int r = row0 + trow * 8 + i;
            float4 o;
            o.x = fmaxf(acc[i][0] + bv.x, 0.0f);
            o.y = fmaxf(acc[i][1] + bv.y, 0.0f);
            o.z = fmaxf(acc[i][2] + bv.z, 0.0f);
            o.w = fmaxf(acc[i][3] + bv.w, 0.0f);
            *reinterpret_cast<float4*>(g_h + (size_t)r * Hc + tcol * 4) = o;
        }
    } else {
        const int r0 = row0 + 64 + mrow + gid;
        const int r1 = r0 + 8;
#pragma unroll
        for (int nt = 0; nt < 8; nt++) {
            int col = nt*8 + 2*tig;
            float2 bv = *reinterpret_cast<const float2*>(b1 + col);
            float2 o0, o1;
            o0.x = fmaxf(cfr[nt][0] + bv.x, 0.0f);
            o0.y = fmaxf(cfr[nt][1] + bv.y, 0.0f);
            o1.x = fmaxf(cfr[nt][2] + bv.x, 0.0f);
            o1.y = fmaxf(cfr[nt][3] + bv.y, 0.0f);
            *reinterpret_cast<float2*>(g_h + (size_t)r0 * Hc + col) = o0;
            *reinterpret_cast<float2*>(g_h + (size_t)r1 * Hc + col) = o1;
        }
    }
}

// ---------------- fused VAE kernel (GEMM1 removed; h from g_h) ----------------
#define VAE_SMEM_FLOATS (8320 + 64*WSP + 64 + 128)

__global__ __launch_bounds__(256, 2)
void vae_kernel(const float* __restrict__ roles, const float* __restrict__ eps,
                const float* __restrict__ W21, const float* __restrict__ b21,
                const float* __restrict__ W22, const float* __restrict__ b22,
                const float* __restrict__ W3,  const float* __restrict__ b3,
                const float* __restrict__ W4,  const float* __restrict__ b4)
{
    extern __shared__ float sm[];
    float* Hs  = sm;                 // 128*65
    float* Ws  = Hs + 8320;          // 64*WSP
    float* red = Ws + 64*WSP;        // 64
    float* rns = red + 64;           // 128

    const int tid  = threadIdx.x;
    const int tcol = tid & 15;
    const int trow = tid >> 4;
    const int row0 = blockIdx.x * 128;
    const int b    = row0 >> 12;

    float acc[8][4];

    // ================= load h from g_h =================
    for (int t = tid; t < 2048; t += 256) {
        int r = t >> 4, c4 = (t & 15) << 2;
        float4 v = *reinterpret_cast<const float4*>(g_h + (size_t)(row0 + r) * Hc + c4);
        Hs[r*65 + c4 + 0] = v.x;
        Hs[r*65 + c4 + 1] = v.y;
        Hs[r*65 + c4 + 2] = v.z;
        Hs[r*65 + c4 + 3] = v.w;
    }
    for (int t = tid; t < 1024; t += 256)
        *reinterpret_cast<float4*>(&Ws[t*4]) = *reinterpret_cast<const float4*>(W22 + t*4);
    __syncthreads();

    float kacc = 0.0f;
    float sreg[8][4];

    // ================= log_var = h@W22 + b22  [fp32] =================
#pragma unroll
    for (int i = 0; i < 8; i++)
#pragma unroll
        for (int j = 0; j < 4; j++) acc[i][j] = 0.0f;
#pragma unroll 8
    for (int k = 0; k < 64; k++) {
        float a[8];
#pragma unroll
        for (int i = 0; i < 8; i++) a[i] = Hs[(trow*8 + i)*65 + k];
        float4 bb = *reinterpret_cast<float4*>(&Ws[k*64 + tcol*4]);
#pragma unroll
        for (int i = 0; i < 8; i++) {
            acc[i][0] += a[i]*bb.x; acc[i][1] += a[i]*bb.y;
            acc[i][2] += a[i]*bb.z; acc[i][3] += a[i]*bb.w;
        }
    }
    {
        float4 bv = *reinterpret_cast<const float4*>(b22 + tcol * 4);
#pragma unroll
        for (int i = 0; i < 8; i++) {
            float bvv[4] = {bv.x, bv.y, bv.z, bv.w};
#pragma unroll
            for (int j = 0; j < 4; j++) {
                float lv = acc[i][j] + bvv[j];
                float ex = expf(lv);
                kacc += (1.0f - LOG_VAR2_C + lv - ex * INV_VAR2_C);
                sreg[i][j] = expf(0.5f * lv) * STD2_C;
            }
        }
    }
    __syncthreads();
    for (int t = tid; t < 1024; t += 256)
        *reinterpret_cast<float4*>(&Ws[t*4]) = *reinterpret_cast<const float4*>(W21 + t*4);
    __syncthreads();

    // ================= mu = h@W21 + b21 ; z = mu + eps*s  [fp32] =================
#pragma unroll
    for (int i = 0; i < 8; i++)
#pragma unroll
        for (int j = 0; j < 4; j++) acc[i][j] = 0.0f;
#pragma unroll 8
    for (int k = 0; k < 64; k++) {
        float a[8];
#pragma unroll
        for (int i = 0; i < 8; i++) a[i] = Hs[(trow*8 + i)*65 + k];
        float4 bb = *reinterpret_cast<float4*>(&Ws[k*64 + tcol*4]);
#pragma unroll
        for (int i = 0; i < 8; i++) {
            acc[i][0] += a[i]*bb.x; acc[i][1] += a[i]*bb.y;
            acc[i][2] += a[i]*bb.z; acc[i][3] += a[i]*bb.w;
        }
    }
    {
        float4 bv = *reinterpret_cast<const float4*>(b21 + tcol * 4);
        float bvv[4] = {bv.x, bv.y, bv.z, bv.w};
#pragma unroll
        for (int i = 0; i < 8; i++) {
            float4 ev = *reinterpret_cast<const float4*>(
                eps + (size_t)(row0 + trow*8 + i) * Hc + tcol * 4);
            float evv[4] = {ev.x, ev.y, ev.z, ev.w};
#pragma unroll
            for (int j = 0; j < 4; j++) {
                float mu = acc[i][j] + bvv[j];
                kacc -= mu * mu * INV_VAR2_C;
                acc[i][j] = mu + evv[j] * sreg[i][j];
            }
        }
    }
    __syncthreads();
#pragma unroll
    for (int i = 0; i < 8; i++) {
        int r = trow * 8 + i;
        Hs[r*65 + tcol*4 + 0] = acc[i][0];
        Hs[r*65 + tcol*4 + 1] = acc[i][1];
        Hs[r*65 + tcol*4 + 2] = acc[i][2];
        Hs[r*65 + tcol*4 + 3] = acc[i][3];
    }
    for (int t = tid; t < 4096; t += 256) {
        int k = t >> 6, n = t & 63;
        Ws[k*WSP + ((n & 7) << 3) + (n >> 3)] = tf32r(W3[t]);
    }
    __syncthreads();

    // ================= role_emb = l2norm(z) (fp32), stored transposed ===========
    if (tid < 128) {
        float ss = 0.0f;
#pragma unroll
        for (int k = 0; k < 64; k++) { float v = Hs[tid*65 + k]; ss += v * v; }
        rns[tid] = 1.0f / fmaxf(sqrtf(ss), 1e-12f);
    }
    __syncthreads();
    {
        const int nloc0 = row0 & (NRc - 1);
        for (int t = tid; t < 128 * 64; t += 256) {
            int k = t >> 7;
            int r = t & 127;
            g_embT[((size_t)b * Hc + k) * NRc + nloc0 + r] = Hs[r*65 + k] * rns[r];
        }
    }
    __syncthreads();
    for (int t = tid; t < 8192; t += 256) {
        int r = t >> 6, k = t & 63;
        Hs[r*65 + k] = tf32r(Hs[r*65 + k]);
    }
    __syncthreads();

    // ================= tf32 HMMA path: g = relu(z@W3+b3); mse(g@W4+b4) ========
    const int wid  = tid >> 5;
    const int lane = tid & 31;
    const int gid  = lane >> 2;
    const int tig  = lane & 3;
    const int mrow = wid * 16;

    uint32_t afr[8][4];
#pragma unroll
    for (int kt = 0; kt < 8; kt++) {
        int k0 = kt * 8;
        afr[kt][0] = __float_as_uint(Hs[(mrow+gid  )*65 + k0+tig  ]);
        afr[kt][1] = __float_as_uint(Hs[(mrow+gid+8)*65 + k0+tig  ]);
        afr[kt][2] = __float_as_uint(Hs[(mrow+gid  )*65 + k0+tig+4]);
        afr[kt][3] = __float_as_uint(Hs[(mrow+gid+8)*65 + k0+tig+4]);
    }
    float cfr[8][4];
#pragma unroll
    for (int nt = 0; nt < 8; nt++)
#pragma unroll
        for (int j = 0; j < 4; j++) cfr[nt][j] = 0.0f;
#pragma unroll
    for (int kt = 0; kt < 8; kt++) {
        const float4* p0 = reinterpret_cast<const float4*>(&Ws[(kt*8+tig  )*WSP + gid*8]);
        const float4* p1 = reinterpret_cast<const float4*>(&Ws[(kt*8+tig+4)*WSP + gid*8]);
        float4 b0a = p0[0], b0b = p0[1];
        float4 b1a = p1[0], b1b = p1[1];
        mma_tf32(cfr[0], afr[kt], __float_as_uint(b0a.x), __float_as_uint(b1a.x));
        mma_tf32(cfr[1], afr[kt], __float_as_uint(b0a.y), __float_as_uint(b1a.y));
        mma_tf32(cfr[2], afr[kt], __float_as_uint(b0a.z), __float_as_uint(b1a.z));
        mma_tf32(cfr[3], afr[kt], __float_as_uint(b0a.w), __float_as_uint(b1a.w));
        mma_tf32(cfr[4], afr[kt], __float_as_uint(b0b.x), __float_as_uint(b1b.x));
        mma_tf32(cfr[5], afr[kt], __float_as_uint(b0b.y), __float_as_uint(b1b.y));
        mma_tf32(cfr[6], afr[kt], __float_as_uint(b0b.z), __float_as_uint(b1b.z));
        mma_tf32(cfr[7], afr[kt], __float_as_uint(b0b.w), __float_as_uint(b1b.w));
    }
    __syncthreads();
#pragma unroll
    for (int nt = 0; nt < 8; nt++) {
        int col = nt*8 + 2*tig;
        float2 b3v = *reinterpret_cast<const float2*>(b3 + col);
        Hs[(mrow+gid  )*65 + col    ] = tf32r(fmaxf(cfr[nt][0] + b3v.x, 0.0f));
        Hs[(mrow+gid  )*65 + col + 1] = tf32r(fmaxf(cfr[nt][1] + b3v.y, 0.0f));
        Hs[(mrow+gid+8)*65 + col    ] = tf32r(fmaxf(cfr[nt][2] + b3v.x, 0.0f));
        Hs[(mrow+gid+8)*65 + col + 1] = tf32r(fmaxf(cfr[nt][3] + b3v.y, 0.0f));
    }
    __syncthreads();
#pragma unroll
    for (int kt = 0; kt < 8; kt++) {
        int k0 = kt * 8;
        afr[kt][0] = __float_as_uint(Hs[(mrow+gid  )*65 + k0+tig  ]);
        afr[kt][1] = __float_as_uint(Hs[(mrow+gid+8)*65 + k0+tig  ]);
        afr[kt][2] = __float_as_uint(Hs[(mrow+gid  )*65 + k0+tig+4]);
        afr[kt][3] = __float_as_uint(Hs[(mrow+gid+8)*65 + k0+tig+4]);
    }

    float msacc = 0.0f;
    for (int ch = 0; ch < 6; ch++) {
        __syncthreads();
        for (int t = tid; t < 4096; t += 256) {
            int k = t >> 6, n = t & 63;
            Ws[k*WSP + ((n & 7) << 3) + (n >> 3)] = tf32r(W4[(size_t)k * DIN + ch*64 + n]);
        }
        __syncthreads();
        float cf[8][4];
#pragma unroll
        for (int nt = 0; nt < 8; nt++)
#pragma unroll
            for (int j = 0; j < 4; j++) cf[nt][j] = 0.0f;
#pragma unroll
        for (int kt = 0; kt < 8; kt++) {
            const float4* p0 = reinterpret_cast<const float4*>(&Ws[(kt*8+tig  )*WSP + gid*8]);
            const float4* p1 = reinterpret_cast<const float4*>(&Ws[(kt*8+tig+4)*WSP + gid*8]);
            float4 b0a = p0[0], b0b = p0[1];
            float4 b1a = p1[0], b1b = p1[1];
            mma_tf32(cf[0], afr[kt], __float_as_uint(b0a.x), __float_as_uint(b1a.x));
            mma_tf32(cf[1], afr[kt], __float_as_uint(b0a.y), __float_as_uint(b1a.y));
            mma_tf32(cf[2], afr[kt], __float_as_uint(b0a.z), __float_as_uint(b1a.z));
            mma_tf32(cf[3], afr[kt], __float_as_uint(b0a.w), __float_as_uint(b1a.w));
            mma_tf32(cf[4], afr[kt], __float_as_uint(b0b.x), __float_as_uint(b1b.x));
            mma_tf32(cf[5], afr[kt], __float_as_uint(b0b.y), __float_as_uint(b1b.y));
            mma_tf32(cf[6], afr[kt], __float_as_uint(b0b.z), __float_as_uint(b1b.z));
            mma_tf32(cf[7], afr[kt], __float_as_uint(b0b.w), __float_as_uint(b1b.w));
        }
#pragma unroll
        for (int nt = 0; nt < 8; nt++) {
            int col = ch*64 + nt*8 + 2*tig;
            float2 b4v = *reinterpret_cast<const float2*>(b4 + col);
            float2 r0v = *reinterpret_cast<const float2*>(
                roles + (size_t)(row0 + mrow + gid    ) * DIN + col);
            float2 r1v = *reinterpret_cast<const float2*>(
                roles + (size_t)(row0 + mrow + gid + 8) * DIN + col);
            float d;
            d = cf[nt][0] + b4v.x - r0v.x; msacc += d*d;
            d = cf[nt][1] + b4v.y - r0v.y; msacc += d*d;
            d = cf[nt][2] + b4v.x - r1v.x; msacc += d*d;
            d = cf[nt][3] + b4v.y - r1v.y; msacc += d*d;
        }
    }

    float ks = kacc, ms = msacc;
#pragma unroll
    for (int off = 16; off > 0; off >>= 1) {
        ks += __shfl_xor_sync(0xffffffffu, ks, off);
        ms += __shfl_xor_sync(0xffffffffu, ms, off);
    }
    __syncthreads();
    if ((tid & 31) == 0) { red[tid >> 5] = ks; red[8 + (tid >> 5)] = ms; }
    __syncthreads();
    if (tid == 0) {
        float kt = 0.0f, mt = 0.0f;
#pragma unroll
        for (int w = 0; w < 8; w++) { kt += red[w]; mt += red[8 + w]; }
        atomicAdd(&g_kld[b], kt);
        atomicAdd(&g_mse[b], mt);
    }
}

// ---------------- vae loss finalize ----------------
__global__ void finalize_kernel(float* __restrict__ out) {
    if (threadIdx.x == 0) {
        float v = 0.0f;
        for (int b = 0; b < Bc; b++) {
            float mse = g_mse[b] * (1.0f / ((float)NRc * (float)DIN));
            float kld = (-0.5f / ((float)NRc * (float)Hc)) * g_kld[b];
            v += mse + kld;
        }
        out[Bc*Ac + Bc + Bc*Hc] = v / (float)Bc;
    }
}

// ---------------- cluster / mbarrier helpers ----------------
__device__ __forceinline__ uint32_t s2u(const void* p) {
    uint32_t a;
    asm("{ .reg .u64 t; cvta.to.shared.u64 t, %1; cvt.u32.u64 %0, t; }" : "=r"(a) : "l"(p));
    return a;
}
__device__ __forceinline__ void mbar_init(uint32_t mbar, uint32_t cnt) {
    asm volatile("mbarrier.init.shared.b64 [%0], %1;" :: "r"(mbar), "r"(cnt) : "memory");
}
__device__ __forceinline__ void mbar_expect_tx(uint32_t mbar, uint32_t bytes) {
    asm volatile("mbarrier.arrive.expect_tx.shared.b64 _, [%0], %1;"
                 :: "r"(mbar), "r"(bytes) : "memory");
}
__device__ __forceinline__ void st_async_b32(uint32_t slot, uint32_t mbar,
                                             uint32_t peer, uint32_t val) {
    uint32_t rs, rb;
    asm("mapa.shared::cluster.u32 %0, %1, %2;" : "=r"(rs) : "r"(slot), "r"(peer));
    asm("mapa.shared::cluster.u32 %0, %1, %2;" : "=r"(rb) : "r"(mbar), "r"(peer));
    asm volatile("st.async.shared::cluster.mbarrier::complete_tx::bytes.b32 [%0], %1, [%2];"
                 :: "r"(rs), "r"(val), "r"(rb) : "memory");
}
__device__ __forceinline__ void mbar_wait_cluster(uint32_t mbar, uint32_t parity) {
    uint32_t done;
    asm volatile("{\n\t.reg .pred p;\n\t"
        "mbarrier.try_wait.parity.acquire.cluster.shared::cta.b64 p, [%1], %2;\n\t"
        "selp.b32 %0, 1, 0, p;\n\t}"
        : "=r"(done) : "r"(mbar), "r"(parity) : "memory");
    while (!done) {
        asm volatile("{\n\t.reg .pred p;\n\t"
            "mbarrier.try_wait.parity.acquire.cluster.shared::cta.b64 p, [%1], %2, 0x989680;\n\t"
            "selp.b32 %0, 1, 0, p;\n\t}"
            : "=r"(done) : "r"(mbar), "r"(parity) : "memory");
    }
}
#define CLUSTER_SYNC() do { \
    asm volatile("barrier.cluster.arrive.aligned;" ::: "memory"); \
    asm volatile("barrier.cluster.wait.aligned;"   ::: "memory"); } while (0)

// ---------------- cluster-parallel selection scan (round-4/6, unchanged) -------
#define CL 4
#define STH 512
#define RPC (NRc / CL)
#define NCACHE 768
#define SCAN_SMEM_FLOATS (1024 + 64*NCACHE)

__global__ __launch_bounds__(STH, 1) __cluster_dims__(CL, 1, 1)
void scan_kernel(const float* __restrict__ contexts, const float* __restrict__ rand_vals,
                 const float* __restrict__ Wc, const float* __restrict__ bc,
                 const float* __restrict__ init_emb, float* __restrict__ out)
{
    extern __shared__ float sm[];
    unsigned long long* mbar = (unsigned long long*)sm;
    float* exchS = sm + 4;
    int*   exchC = (int*)(sm + 12);
    int*   seli  = (int*)(sm + 20);
    float* scal  = sm + 21;
    float* wred  = sm + 28;
    float* wexc  = sm + 44;
    float* ctxs  = sm + 60;
    float* bcs   = sm + 188;
    float* hist  = sm + 252;
    float* cur   = sm + 316;
    float* tmp   = sm + 380;
    float* cvec  = sm + 444;
    float* cpart = sm + 508;
    float* embc  = sm + 1024;

    const int b    = blockIdx.x >> 2;
    const int rank = blockIdx.x & 3;
    const int tid  = threadIdx.x;
    const int lane = tid & 31;
    const int wid  = tid >> 5;

    const uint32_t mbarS_a = s2u(&mbar[0]);
    const uint32_t mbarC_a = s2u(&mbar[1]);

    const float* embT = g_embT + (size_t)b * Hc * NRc;

    const int col  = tid & 63;
    const int irow = (tid >> 6) * 24;
    float wreg[24];
#pragma unroll
    for (int i = 0; i < 24; i++) wreg[i] = Wc[(size_t)(irow + i) * 64 + col];

    for (int t = tid; t < 64 * NCACHE / 4; t += STH) {
        int k  = t / (NCACHE / 4);
        int n4 = (t % (NCACHE / 4)) * 4;
        *reinterpret_cast<float4*>(&embc[k * NCACHE + n4]) =
            *reinterpret_cast<const float4*>(embT + (size_t)k * NRc + rank * RPC + n4);
    }
    if (tid < 128) ctxs[tid] = contexts[b * DCTX + tid];
    if (tid < 64)  { bcs[tid] = bc[tid]; float iv = init_emb[tid]; hist[tid] = iv; cur[tid] = iv; }
    if (tid == 0)  {
        scal[0] = 0.0f;
        mbar_init(mbarS_a, 1);
        mbar_init(mbarC_a, 1);
    }
    __syncthreads();
    CLUSTER_SYNC();

    for (int step = 0; step < Ac; step++) {
        const uint32_t par = (uint32_t)(step & 1);
        const uint32_t slotS = s2u(&exchS[(step & 1) * 4 + rank]);
        const uint32_t slotC = s2u(&exchC[(step & 1) * 4 + rank]);

        if (tid == 0) {
            mbar_expect_tx(mbarS_a, 16);
            mbar_expect_tx(mbarC_a, 16);
            seli[0] = 0x7fffffff;
        }
        if (tid < 64) tmp[tid] = hist[tid] + cur[tid];
        __syncthreads();
        if (wid == 0) {
            float x0 = tmp[lane], x1 = tmp[lane + 32];
            float s = x0 + x1;
#pragma unroll
            for (int off = 16; off > 0; off >>= 1) s += __shfl_xor_sync(0xffffffffu, s, off);
            float mean = s * (1.0f / 64.0f);
            float d0 = x0 - mean, d1 = x1 - mean;
            float vs = d0*d0 + d1*d1;
#pragma unroll
            for (int off = 16; off > 0; off >>= 1) vs += __shfl_xor_sync(0xffffffffu, vs, off);
            if (lane == 0) {
                scal[1] = mean;
                scal[2] = 1.0f / sqrtf(vs * (1.0f / 64.0f) + 1e-5f);
            }
        }
        __syncthreads();
        if (tid < 64) hist[tid] = (tmp[tid] - scal[1]) * scal[2];
        __syncthreads();

        {
            float s = 0.0f;
#pragma unroll
            for (int i = 0; i < 24; i++) {
                int gi = irow + i;
                float x = (gi < 128) ? ctxs[gi] : hist[gi - 128];
                s = fmaf(x, wreg[i], s);
            }
            cpart[(tid >> 6) * 64 + col] = s;
        }
        __syncthreads();
        if (tid < 64) {
            float s = bcs[tid];
#pragma unroll
            for (int p = 0; p < 8; p++) s += cpart[p*64 + tid];
            cvec[tid] = s;
        }
        __syncthreads();
        if (wid == 0) {
            float c0 = cvec[lane], c1 = cvec[lane + 32];
            float ss = c0*c0 + c1*c1;
#pragma unroll
            for (int off = 16; off > 0; off >>= 1) ss += __shfl_xor_sync(0xffffffffu, ss, off);
            if (lane == 0) scal[3] = 1.0f / fmaxf(sqrtf(ss), 1e-12f);
        }
        __syncthreads();
        if (tid < 64) cvec[tid] *= scal[3];
        __syncthreads();

        float sx = 0.f, sy = 0.f;
        if (tid < NCACHE / 2) {
            const float* ep = embc + 2 * tid;
#pragma unroll 8
            for (int k = 0; k < 64; k++) {
                float2 v = *reinterpret_cast<const float2*>(ep + k * NCACHE);
                float ck = cvec[k];
                sx = fmaf(v.x, ck, sx); sy = fmaf(v.y, ck, sy);
            }
        } else {
            const float* ep = embT + rank * RPC + 2 * tid;
#pragma unroll 16
            for (int k = 0; k < 64; k++) {
                float2 v = *reinterpret_cast<const float2*>(ep + (size_t)k * NRc);
                float ck = cvec[k];
                sx = fmaf(v.x, ck, sx); sy = fmaf(v.y, ck, sy);
            }
        }
        float e0 = expf(sx), e1 = expf(sy);
        float t2 = e0 + e1;

        float incl = t2;
#pragma unroll
        for (int off = 1; off < 32; off <<= 1) {
            float n = __shfl_up_sync(0xffffffffu, incl, off);
            if (lane >= off) incl += n;
        }
        if (lane == 31) wred[wid] = incl;
        __syncthreads();
        if (tid == 0) {
            float s = 0.0f;
#pragma unroll
            for (int w = 0; w < 16; w++) { float v = wred[w]; wexc[w] = s; s += v; }
            scal[4] = s;
        }
        __syncthreads();
        float S_local  = scal[4];
        float excl_thr = wexc[wid] + (incl - t2);

        if (tid < CL) st_async_b32(slotS, mbarS_a, (uint32_t)tid, __float_as_uint(S_local));
        mbar_wait_cluster(mbarS_a, par);
        float S_tot = 0.0f, pre = 0.0f;
#pragma unroll
        for (int r = 0; r < CL; r++) {
            float v = exchS[(step & 1) * 4 + r];
            if (r < rank) pre += v;
            S_tot += v;
        }

        float T = rand_vals[b * Ac + step] * S_tot;
        float base = pre + excl_thr;
        int cand = 0x7fffffff;
        int gr = rank * RPC + tid * 2;
        if      (base + e0 > T) cand = gr;
        else if (base + t2 > T) cand = gr + 1;
        if (cand != 0x7fffffff) atomicMin(seli, cand);
        __syncthreads();
        int lc = seli[0];
        if (tid < CL) st_async_b32(slotC, mbarC_a, (uint32_t)tid, (uint32_t)lc);
        mbar_wait_cluster(mbarC_a, par);
        int sel = 0x7fffffff;
#pragma unroll
        for (int r = 0; r < CL; r++) sel = min(sel, exchC[(step & 1) * 4 + r]);
        if (sel == 0x7fffffff) sel = 0;

        if (tid < 64) cur[tid] = embT[(size_t)tid * NRc + sel];
        __syncthreads();
        if (wid == 0) {
            float d = cur[lane] * cvec[lane] + cur[lane + 32] * cvec[lane + 32];
#pragma unroll
            for (int off = 16; off > 0; off >>= 1) d += __shfl_xor_sync(0xffffffffu, d, off);
            if (lane == 0) scal[0] += d - logf(S_tot);
        }
        if (rank == 0 && tid == 0) out[b * Ac + step] = (float)sel;
        __syncthreads();
    }

    if (rank == 0 && tid == 0) out[Bc*Ac + b] = scal[0];
    if (rank == 0 && tid < 64) out[Bc*Ac + Bc + b*Hc + tid] = hist[tid];
    CLUSTER_SYNC();
}

// ---------------- launcher ----------------
extern "C" void kernel_launch(void* const* d_in, const int* in_sizes, int n_in,
                              void* d_out, int out_size) {
    const float* roles     = (const float*)d_in[0];
    const float* contexts  = (const float*)d_in[1];
    const float* eps       = (const float*)d_in[2];
    const float* rand_vals = (const float*)d_in[3];
    const float* W1  = (const float*)d_in[5];
    const float* b1  = (const float*)d_in[6];
    const float* W21 = (const float*)d_in[7];
    const float* b21 = (const float*)d_in[8];
    const float* W22 = (const float*)d_in[9];
    const float* b22 = (const float*)d_in[10];
    const float* W3  = (const float*)d_in[11];
    const float* b3  = (const float*)d_in[12];
    const float* W4  = (const float*)d_in[13];
    const float* b4  = (const float*)d_in[14];
    const float* Wc  = (const float*)d_in[15];
    const float* bc  = (const float*)d_in[16];
    const float* init_emb = (const float*)d_in[17];
    float* out = (float*)d_out;

    const int g1_smem   = G1_SMEM_FLOATS   * (int)sizeof(float);
    const int vae_smem  = VAE_SMEM_FLOATS  * (int)sizeof(float);
    const int scan_smem = SCAN_SMEM_FLOATS * (int)sizeof(float);
    cudaFuncSetAttribute(gemm1_kernel, cudaFuncAttributeMaxDynamicSharedMemorySize, g1_smem);
    cudaFuncSetAttribute(vae_kernel,  cudaFuncAttributeMaxDynamicSharedMemorySize, vae_smem);
    cudaFuncSetAttribute(scan_kernel, cudaFuncAttributeMaxDynamicSharedMemorySize, scan_smem);

    zero_kernel<<<1, 32>>>();
    gemm1_kernel<<<MTOT / 128, 256, g1_smem>>>(roles, W1, b1);
    vae_kernel<<<MTOT / 128, 256, vae_smem>>>(roles, eps, W21, b21,
                                              W22, b22, W3, b3, W4, b4);
    finalize_kernel<<<1, 1>>>(out);
    scan_kernel<<<Bc * CL, STH, scan_smem>>>(contexts, rand_vals, Wc, bc,
                                             init_emb, out);
}

// round 10
// speedup vs baseline: 1.4225x; 1.4225x over previous
#include <cuda_runtime.h>
#include <math.h>
#include <stdint.h>

// ---------------- problem constants ----------------
#define Bc   32
#define NRc  4096
#define DIN  384
#define DCTX 128
#define Hc   64
#define Ac   16
#define MTOT (Bc * NRc)

#define LOG_VAR2_C  (-4.6051701859880914f)
#define INV_VAR2_C  (100.0f)
#define STD2_C      (0.1f)

// ---------------- device scratch ----------------
__device__ float g_embT[(size_t)Bc * Hc * NRc];   // [b][k][n]
__device__ float g_mse[Bc];
__device__ float g_kld[Bc];

// ---------------- zero accumulators ----------------
__global__ void zero_kernel() {
    int t = threadIdx.x;
    if (t < Bc) { g_mse[t] = 0.0f; g_kld[t] = 0.0f; }
}

// ---------------- tf32 helpers ----------------
__device__ __forceinline__ float tf32r(float x) {
    uint32_t u; asm("cvt.rna.tf32.f32 %0, %1;" : "=r"(u) : "f"(x));
    return __uint_as_float(u);
}
__device__ __forceinline__ void mma_tf32(float c[4], const uint32_t a[4],
                                         uint32_t b0, uint32_t b1) {
    asm volatile("mma.sync.aligned.m16n8k8.row.col.f32.tf32.tf32.f32 "
        "{%0,%1,%2,%3}, {%4,%5,%6,%7}, {%8,%9}, {%0,%1,%2,%3};"
        : "+f"(c[0]), "+f"(c[1]), "+f"(c[2]), "+f"(c[3])
        : "r"(a[0]), "r"(a[1]), "r"(a[2]), "r"(a[3]), "r"(b0), "r"(b1));
}

// WsP row stride (floats): 68 = conflict-free bank-start spread for LDS.128
#define WSP 68

// ---------------- fused VAE kernel (round-6 champion + GEMM1 prefetch) ---------
// z/emb/kld path: exact fp32 scalar. x_hat path: tf32 HMMA, permuted B layout.
#define VAE_SMEM_FLOATS (2048 + 1024 + 8320 + 64*WSP + 64 + 128)

__global__ __launch_bounds__(256, 2)
void vae_kernel(const float* __restrict__ roles, const float* __restrict__ eps,
                const float* __restrict__ W1,  const float* __restrict__ b1,
                const float* __restrict__ W21, const float* __restrict__ b21,
                const float* __restrict__ W22, const float* __restrict__ b22,
                const float* __restrict__ W3,  const float* __restrict__ b3,
                const float* __restrict__ W4,  const float* __restrict__ b4)
{
    extern __shared__ float sm[];
    float* As  = sm;                 // 16*128
    float* Bs  = As + 2048;          // 16*64
    float* Hs  = Bs + 1024;          // 128*65
    float* Ws  = Hs + 8320;          // 64*WSP (fp32 GEMMs use first 64*64)
    float* red = Ws + 64*WSP;        // 64
    float* rns = red + 64;           // 128

    const int tid  = threadIdx.x;
    const int tcol = tid & 15;
    const int trow = tid >> 4;
    const int row0 = blockIdx.x * 128;
    const int b    = row0 >> 12;

    float acc[8][4];

    // ================= GEMM1: h = relu(roles @ W1 + b1)  [fp32, prefetched] =====
#pragma unroll
    for (int i = 0; i < 8; i++)
#pragma unroll
        for (int j = 0; j < 4; j++) acc[i][j] = 0.0f;

    // per-thread fixed staging coordinates
    const int am0 = tid >> 2;                 // A slot 0: m row
    const int ak0 = (tid & 3) * 4;            //           k quad
    const int am1 = (tid + 256) >> 2;         // A slot 1
    const int ak1 = ((tid + 256) & 3) * 4;
    const int bk  = tid >> 4;                 // B: k row
    const int bj4 = (tid & 15) * 4;           //    n quad

    float4 va0, va1, vb;
    // preload tile 0
    va0 = *reinterpret_cast<const float4*>(roles + (size_t)(row0 + am0) * DIN + ak0);
    va1 = *reinterpret_cast<const float4*>(roles + (size_t)(row0 + am1) * DIN + ak1);
    vb  = *reinterpret_cast<const float4*>(W1 + (size_t)bk * Hc + bj4);

    for (int t = 0; t < 24; t++) {
        // scatter current tile regs -> smem
        As[(ak0 + 0) * 128 + am0] = va0.x;
        As[(ak0 + 1) * 128 + am0] = va0.y;
        As[(ak0 + 2) * 128 + am0] = va0.z;
        As[(ak0 + 3) * 128 + am0] = va0.w;
        As[(ak1 + 0) * 128 + am1] = va1.x;
        As[(ak1 + 1) * 128 + am1] = va1.y;
        As[(ak1 + 2) * 128 + am1] = va1.z;
        As[(ak1 + 3) * 128 + am1] = va1.w;
        *reinterpret_cast<float4*>(&Bs[bk * 64 + bj4]) = vb;
        __syncthreads();

        // prefetch next tile (latency hidden behind compute)
        if (t + 1 < 24) {
            const int kt = (t + 1) * 16;
            va0 = *reinterpret_cast<const float4*>(
                roles + (size_t)(row0 + am0) * DIN + kt + ak0);
            va1 = *reinterpret_cast<const float4*>(
                roles + (size_t)(row0 + am1) * DIN + kt + ak1);
            vb  = *reinterpret_cast<const float4*>(
                W1 + (size_t)(kt + bk) * Hc + bj4);
        }

#pragma unroll
        for (int k = 0; k < 16; k++) {
            float a[8];
            *reinterpret_cast<float4*>(&a[0]) = *reinterpret_cast<float4*>(&As[k*128 + trow*8]);
            *reinterpret_cast<float4*>(&a[4]) = *reinterpret_cast<float4*>(&As[k*128 + trow*8 + 4]);
            float4 bb = *reinterpret_cast<float4*>(&Bs[k*64 + tcol*4]);
#pragma unroll
            for (int i = 0; i < 8; i++) {
                acc[i][0] += a[i] * bb.x;
                acc[i][1] += a[i] * bb.y;
                acc[i][2] += a[i] * bb.z;
                acc[i][3] += a[i] * bb.w;
            }
        }
        __syncthreads();
    }
    {
        float4 bv = *reinterpret_cast<const float4*>(b1 + tcol * 4);
#pragma unroll
        for (int i = 0; i < 8; i++) {
            int r = trow * 8 + i;
            Hs[r*65 + tcol*4 + 0] = fmaxf(acc[i][0] + bv.x, 0.0f);
            Hs[r*65 + tcol*4 + 1] = fmaxf(acc[i][1] + bv.y, 0.0f);
            Hs[r*65 + tcol*4 + 2] = fmaxf(acc[i][2] + bv.z, 0.0f);
            Hs[r*65 + tcol*4 + 3] = fmaxf(acc[i][3] + bv.w, 0.0f);
        }
    }
    for (int t = tid; t < 1024; t += 256)
        *reinterpret_cast<float4*>(&Ws[t*4]) = *reinterpret_cast<const float4*>(W22 + t*4);
    __syncthreads();

    float kacc = 0.0f;
    float sreg[8][4];

    // ================= log_var = h@W22 + b22  [fp32] =================
#pragma unroll
    for (int i = 0; i < 8; i++)
#pragma unroll
        for (int j = 0; j < 4; j++) acc[i][j] = 0.0f;
#pragma unroll 8
    for (int k = 0; k < 64; k++) {
        float a[8];
#pragma unroll
        for (int i = 0; i < 8; i++) a[i] = Hs[(trow*8 + i)*65 + k];
        float4 bb = *reinterpret_cast<float4*>(&Ws[k*64 + tcol*4]);
#pragma unroll
        for (int i = 0; i < 8; i++) {
            acc[i][0] += a[i]*bb.x; acc[i][1] += a[i]*bb.y;
            acc[i][2] += a[i]*bb.z; acc[i][3] += a[i]*bb.w;
        }
    }
    {
        float4 bv = *reinterpret_cast<const float4*>(b22 + tcol * 4);
#pragma unroll
        for (int i = 0; i < 8; i++) {
            float bvv[4] = {bv.x, bv.y, bv.z, bv.w};
#pragma unroll
            for (int j = 0; j < 4; j++) {
                float lv = acc[i][j] + bvv[j];
                float ex = expf(lv);
                kacc += (1.0f - LOG_VAR2_C + lv - ex * INV_VAR2_C);
                sreg[i][j] = expf(0.5f * lv) * STD2_C;
            }
        }
    }
    __syncthreads();
    for (int t = tid; t < 1024; t += 256)
        *reinterpret_cast<float4*>(&Ws[t*4]) = *reinterpret_cast<const float4*>(W21 + t*4);
    __syncthreads();

    // ================= mu = h@W21 + b21 ; z = mu + eps*s  [fp32] =================
#pragma unroll
    for (int i = 0; i < 8; i++)
#pragma unroll
        for (int j = 0; j < 4; j++) acc[i][j] = 0.0f;
#pragma unroll 8
    for (int k = 0; k < 64; k++) {
        float a[8];
#pragma unroll
        for (int i = 0; i < 8; i++) a[i] = Hs[(trow*8 + i)*65 + k];
        float4 bb = *reinterpret_cast<float4*>(&Ws[k*64 + tcol*4]);
#pragma unroll
        for (int i = 0; i < 8; i++) {
            acc[i][0] += a[i]*bb.x; acc[i][1] += a[i]*bb.y;
            acc[i][2] += a[i]*bb.z; acc[i][3] += a[i]*bb.w;
        }
    }
    {
        float4 bv = *reinterpret_cast<const float4*>(b21 + tcol * 4);
        float bvv[4] = {bv.x, bv.y, bv.z, bv.w};
#pragma unroll
        for (int i = 0; i < 8; i++) {
            float4 ev = *reinterpret_cast<const float4*>(
                eps + (size_t)(row0 + trow*8 + i) * Hc + tcol * 4);
            float evv[4] = {ev.x, ev.y, ev.z, ev.w};
#pragma unroll
            for (int j = 0; j < 4; j++) {
                float mu = acc[i][j] + bvv[j];
                kacc -= mu * mu * INV_VAR2_C;
                acc[i][j] = mu + evv[j] * sreg[i][j];
            }
        }
    }
    __syncthreads();
    // z (fp32) -> Hs ; stage Ws = permuted tf32(W3)
#pragma unroll
    for (int i = 0; i < 8; i++) {
        int r = trow * 8 + i;
        Hs[r*65 + tcol*4 + 0] = acc[i][0];
        Hs[r*65 + tcol*4 + 1] = acc[i][1];
        Hs[r*65 + tcol*4 + 2] = acc[i][2];
        Hs[r*65 + tcol*4 + 3] = acc[i][3];
    }
    for (int t = tid; t < 4096; t += 256) {
        int k = t >> 6, n = t & 63;
        Ws[k*WSP + ((n & 7) << 3) + (n >> 3)] = tf32r(W3[t]);
    }
    __syncthreads();

    // ================= role_emb = l2norm(z) (fp32), stored transposed ===========
    if (tid < 128) {
        float ss = 0.0f;
#pragma unroll
        for (int k = 0; k < 64; k++) { float v = Hs[tid*65 + k]; ss += v * v; }
        rns[tid] = 1.0f / fmaxf(sqrtf(ss), 1e-12f);
    }
    __syncthreads();
    {
        const int nloc0 = row0 & (NRc - 1);
        for (int t = tid; t < 128 * 64; t += 256) {
            int k = t >> 7;
            int r = t & 127;
            g_embT[((size_t)b * Hc + k) * NRc + nloc0 + r] = Hs[r*65 + k] * rns[r];
        }
    }
    __syncthreads();
    // in-place round z -> tf32 for the mse path
    for (int t = tid; t < 8192; t += 256) {
        int r = t >> 6, k = t & 63;
        Hs[r*65 + k] = tf32r(Hs[r*65 + k]);
    }
    __syncthreads();

    // ================= tf32 HMMA path: g = relu(z@W3+b3); mse(g@W4+b4) ========
    const int wid  = tid >> 5;          // 8 warps x 16 rows
    const int lane = tid & 31;
    const int gid  = lane >> 2;         // 0..7
    const int tig  = lane & 3;          // 0..3
    const int mrow = wid * 16;

    uint32_t afr[8][4];
#pragma unroll
    for (int kt = 0; kt < 8; kt++) {
        int k0 = kt * 8;
        afr[kt][0] = __float_as_uint(Hs[(mrow+gid  )*65 + k0+tig  ]);
        afr[kt][1] = __float_as_uint(Hs[(mrow+gid+8)*65 + k0+tig  ]);
        afr[kt][2] = __float_as_uint(Hs[(mrow+gid  )*65 + k0+tig+4]);
        afr[kt][3] = __float_as_uint(Hs[(mrow+gid+8)*65 + k0+tig+4]);
    }
    float cfr[8][4];
#pragma unroll
    for (int nt = 0; nt < 8; nt++)
#pragma unroll
        for (int j = 0; j < 4; j++) cfr[nt][j] = 0.0f;
#pragma unroll
    for (int kt = 0; kt < 8; kt++) {
        const float4* p0 = reinterpret_cast<const float4*>(&Ws[(kt*8+tig  )*WSP + gid*8]);
        const float4* p1 = reinterpret_cast<const float4*>(&Ws[(kt*8+tig+4)*WSP + gid*8]);
        float4 b0a = p0[0], b0b = p0[1];
        float4 b1a = p1[0], b1b = p1[1];
        mma_tf32(cfr[0], afr[kt], __float_as_uint(b0a.x), __float_as_uint(b1a.x));
        mma_tf32(cfr[1], afr[kt], __float_as_uint(b0a.y), __float_as_uint(b1a.y));
        mma_tf32(cfr[2], afr[kt], __float_as_uint(b0a.z), __float_as_uint(b1a.z));
        mma_tf32(cfr[3], afr[kt], __float_as_uint(b0a.w), __float_as_uint(b1a.w));
        mma_tf32(cfr[4], afr[kt], __float_as_uint(b0b.x), __float_as_uint(b1b.x));
        mma_tf32(cfr[5], afr[kt], __float_as_uint(b0b.y), __float_as_uint(b1b.y));
        mma_tf32(cfr[6], afr[kt], __float_as_uint(b0b.z), __float_as_uint(b1b.z));
        mma_tf32(cfr[7], afr[kt], __float_as_uint(b0b.w), __float_as_uint(b1b.w));
    }
    __syncthreads();   // all reads of Hs(z) / Ws(W3) done
    // g = tf32(relu(c + b3)) -> Hs
#pragma unroll
    for (int nt = 0; nt < 8; nt++) {
        int col = nt*8 + 2*tig;
        float2 b3v = *reinterpret_cast<const float2*>(b3 + col);
        Hs[(mrow+gid  )*65 + col    ] = tf32r(fmaxf(cfr[nt][0] + b3v.x, 0.0f));
        Hs[(mrow+gid  )*65 + col + 1] = tf32r(fmaxf(cfr[nt][1] + b3v.y, 0.0f));
        Hs[(mrow+gid+8)*65 + col    ] = tf32r(fmaxf(cfr[nt][2] + b3v.x, 0.0f));
        Hs[(mrow+gid+8)*65 + col + 1] = tf32r(fmaxf(cfr[nt][3] + b3v.y, 0.0f));
    }
    __syncthreads();
    // A fragments of g (reused across all 6 chunks)
#pragma unroll
    for (int kt = 0; kt < 8; kt++) {
        int k0 = kt * 8;
        afr[kt][0] = __float_as_uint(Hs[(mrow+gid  )*65 + k0+tig  ]);
        afr[kt][1] = __float_as_uint(Hs[(mrow+gid+8)*65 + k0+tig  ]);
        afr[kt][2] = __float_as_uint(Hs[(mrow+gid  )*65 + k0+tig+4]);
        afr[kt][3] = __float_as_uint(Hs[(mrow+gid+8)*65 + k0+tig+4]);
    }

    float msacc = 0.0f;
    for (int ch = 0; ch < 6; ch++) {
        __syncthreads();   // prev chunk's Ws reads done
        for (int t = tid; t < 4096; t += 256) {
            int k = t >> 6, n = t & 63;
            Ws[k*WSP + ((n & 7) << 3) + (n >> 3)] = tf32r(W4[(size_t)k * DIN + ch*64 + n]);
        }
        __syncthreads();
        float cf[8][4];
#pragma unroll
        for (int nt = 0; nt < 8; nt++)
#pragma unroll
            for (int j = 0; j < 4; j++) cf[nt][j] = 0.0f;
#pragma unroll
        for (int kt = 0; kt < 8; kt++) {
            const float4* p0 = reinterpret_cast<const float4*>(&Ws[(kt*8+tig  )*WSP + gid*8]);
            const float4* p1 = reinterpret_cast<const float4*>(&Ws[(kt*8+tig+4)*WSP + gid*8]);
            float4 b0a = p0[0], b0b = p0[1];
            float4 b1a = p1[0], b1b = p1[1];
            mma_tf32(cf[0], afr[kt], __float_as_uint(b0a.x), __float_as_uint(b1a.x));
            mma_tf32(cf[1], afr[kt], __float_as_uint(b0a.y), __float_as_uint(b1a.y));
            mma_tf32(cf[2], afr[kt], __float_as_uint(b0a.z), __float_as_uint(b1a.z));
            mma_tf32(cf[3], afr[kt], __float_as_uint(b0a.w), __float_as_uint(b1a.w));
            mma_tf32(cf[4], afr[kt], __float_as_uint(b0b.x), __float_as_uint(b1b.x));
            mma_tf32(cf[5], afr[kt], __float_as_uint(b0b.y), __float_as_uint(b1b.y));
            mma_tf32(cf[6], afr[kt], __float_as_uint(b0b.z), __float_as_uint(b1b.z));
            mma_tf32(cf[7], afr[kt], __float_as_uint(b0b.w), __float_as_uint(b1b.w));
        }
#pragma unroll
        for (int nt = 0; nt < 8; nt++) {
            int col = ch*64 + nt*8 + 2*tig;
            float2 b4v = *reinterpret_cast<const float2*>(b4 + col);
            float2 r0v = *reinterpret_cast<const float2*>(
                roles + (size_t)(row0 + mrow + gid    ) * DIN + col);
            float2 r1v = *reinterpret_cast<const float2*>(
                roles + (size_t)(row0 + mrow + gid + 8) * DIN + col);
            float d;
            d = cf[nt][0] + b4v.x - r0v.x; msacc += d*d;
            d = cf[nt][1] + b4v.y - r0v.y; msacc += d*d;
            d = cf[nt][2] + b4v.x - r1v.x; msacc += d*d;
            d = cf[nt][3] + b4v.y - r1v.y; msacc += d*d;
        }
    }

    // ================= block reduce kld / mse =================
    float ks = kacc, ms = msacc;
#pragma unroll
    for (int off = 16; off > 0; off >>= 1) {
        ks += __shfl_xor_sync(0xffffffffu, ks, off);
        ms += __shfl_xor_sync(0xffffffffu, ms, off);
    }
    __syncthreads();
    if ((tid & 31) == 0) { red[tid >> 5] = ks; red[8 + (tid >> 5)] = ms; }
    __syncthreads();
    if (tid == 0) {
        float kt = 0.0f, mt = 0.0f;
#pragma unroll
        for (int w = 0; w < 8; w++) { kt += red[w]; mt += red[8 + w]; }
        atomicAdd(&g_kld[b], kt);
        atomicAdd(&g_mse[b], mt);
    }
}

// ---------------- cluster / mbarrier helpers ----------------
__device__ __forceinline__ uint32_t s2u(const void* p) {
    uint32_t a;
    asm("{ .reg .u64 t; cvta.to.shared.u64 t, %1; cvt.u32.u64 %0, t; }" : "=r"(a) : "l"(p));
    return a;
}
__device__ __forceinline__ void mbar_init(uint32_t mbar, uint32_t cnt) {
    asm volatile("mbarrier.init.shared.b64 [%0], %1;" :: "r"(mbar), "r"(cnt) : "memory");
}
__device__ __forceinline__ void mbar_expect_tx(uint32_t mbar, uint32_t bytes) {
    asm volatile("mbarrier.arrive.expect_tx.shared.b64 _, [%0], %1;"
                 :: "r"(mbar), "r"(bytes) : "memory");
}
__device__ __forceinline__ void st_async_b32(uint32_t slot, uint32_t mbar,
                                             uint32_t peer, uint32_t val) {
    uint32_t rs, rb;
    asm("mapa.shared::cluster.u32 %0, %1, %2;" : "=r"(rs) : "r"(slot), "r"(peer));
    asm("mapa.shared::cluster.u32 %0, %1, %2;" : "=r"(rb) : "r"(mbar), "r"(peer));
    asm volatile("st.async.shared::cluster.mbarrier::complete_tx::bytes.b32 [%0], %1, [%2];"
                 :: "r"(rs), "r"(val), "r"(rb) : "memory");
}
__device__ __forceinline__ void mbar_wait_cluster(uint32_t mbar, uint32_t parity) {
    uint32_t done;
    asm volatile("{\n\t.reg .pred p;\n\t"
        "mbarrier.try_wait.parity.acquire.cluster.shared::cta.b64 p, [%1], %2;\n\t"
        "selp.b32 %0, 1, 0, p;\n\t}"
        : "=r"(done) : "r"(mbar), "r"(parity) : "memory");
    while (!done) {
        asm volatile("{\n\t.reg .pred p;\n\t"
            "mbarrier.try_wait.parity.acquire.cluster.shared::cta.b64 p, [%1], %2, 0x989680;\n\t"
            "selp.b32 %0, 1, 0, p;\n\t}"
            : "=r"(done) : "r"(mbar), "r"(parity) : "memory");
    }
}
#define CLUSTER_SYNC() do { \
    asm volatile("barrier.cluster.arrive.aligned;" ::: "memory"); \
    asm volatile("barrier.cluster.wait.aligned;"   ::: "memory"); } while (0)

// ---------------- cluster-parallel selection scan (+ folded finalize) ----------
#define CL 4
#define STH 512
#define RPC (NRc / CL)
#define NCACHE 768
#define SCAN_SMEM_FLOATS (1024 + 64*NCACHE)

__global__ __launch_bounds__(STH, 1) __cluster_dims__(CL, 1, 1)
void scan_kernel(const float* __restrict__ contexts, const float* __restrict__ rand_vals,
                 const float* __restrict__ Wc, const float* __restrict__ bc,
                 const float* __restrict__ init_emb, float* __restrict__ out)
{
    extern __shared__ float sm[];
    unsigned long long* mbar = (unsigned long long*)sm;
    float* exchS = sm + 4;
    int*   exchC = (int*)(sm + 12);
    int*   seli  = (int*)(sm + 20);
    float* scal  = sm + 21;
    float* wred  = sm + 28;
    float* wexc  = sm + 44;
    float* ctxs  = sm + 60;
    float* bcs   = sm + 188;
    float* hist  = sm + 252;
    float* cur   = sm + 316;
    float* tmp   = sm + 380;
    float* cvec  = sm + 444;
    float* cpart = sm + 508;
    float* embc  = sm + 1024;

    const int b    = blockIdx.x >> 2;
    const int rank = blockIdx.x & 3;
    const int tid  = threadIdx.x;
    const int lane = tid & 31;
    const int wid  = tid >> 5;

    // folded finalize: vae_loss (g_mse/g_kld complete — vae ended at kernel boundary)
    if (blockIdx.x == 0 && tid == 0) {
        float v = 0.0f;
        for (int bb = 0; bb < Bc; bb++) {
            float mse = g_mse[bb] * (1.0f / ((float)NRc * (float)DIN));
            float kld = (-0.5f / ((float)NRc * (float)Hc)) * g_kld[bb];
            v += mse + kld;
        }
        out[Bc*Ac + Bc + Bc*Hc] = v / (float)Bc;
    }

    const uint32_t mbarS_a = s2u(&mbar[0]);
    const uint32_t mbarC_a = s2u(&mbar[1]);

    const float* embT = g_embT + (size_t)b * Hc * NRc;

    const int col  = tid & 63;
    const int irow = (tid >> 6) * 24;
    float wreg[24];
#pragma unroll
    for (int i = 0; i < 24; i++) wreg[i] = Wc[(size_t)(irow + i) * 64 + col];

    for (int t = tid; t < 64 * NCACHE / 4; t += STH) {
        int k  = t / (NCACHE / 4);
        int n4 = (t % (NCACHE / 4)) * 4;
        *reinterpret_cast<float4*>(&embc[k * NCACHE + n4]) =
            *reinterpret_cast<const float4*>(embT + (size_t)k * NRc + rank * RPC + n4);
    }
    if (tid < 128) ctxs[tid] = contexts[b * DCTX + tid];
    if (tid < 64)  { bcs[tid] = bc[tid]; float iv = init_emb[tid]; hist[tid] = iv; cur[tid] = iv; }
    if (tid == 0)  {
        scal[0] = 0.0f;
        mbar_init(mbarS_a, 1);
        mbar_init(mbarC_a, 1);
    }
    __syncthreads();
    CLUSTER_SYNC();

    for (int step = 0; step < Ac; step++) {
        const uint32_t par = (uint32_t)(step & 1);
        const uint32_t slotS = s2u(&exchS[(step & 1) * 4 + rank]);
        const uint32_t slotC = s2u(&exchC[(step & 1) * 4 + rank]);

        if (tid == 0) {
            mbar_expect_tx(mbarS_a, 16);
            mbar_expect_tx(mbarC_a, 16);
            seli[0] = 0x7fffffff;
        }
        if (tid < 64) tmp[tid] = hist[tid] + cur[tid];
        __syncthreads();
        if (wid == 0) {
            float x0 = tmp[lane], x1 = tmp[lane + 32];
            float s = x0 + x1;
#pragma unroll
            for (int off = 16; off > 0; off >>= 1) s += __shfl_xor_sync(0xffffffffu, s, off);
            float mean = s * (1.0f / 64.0f);
            float d0 = x0 - mean, d1 = x1 - mean;
            float vs = d0*d0 + d1*d1;
#pragma unroll
            for (int off = 16; off > 0; off >>= 1) vs += __shfl_xor_sync(0xffffffffu, vs, off);
            if (lane == 0) {
                scal[1] = mean;
                scal[2] = 1.0f / sqrtf(vs * (1.0f / 64.0f) + 1e-5f);
            }
        }
        __syncthreads();
        if (tid < 64) hist[tid] = (tmp[tid] - scal[1]) * scal[2];
        __syncthreads();

        {
            float s = 0.0f;
#pragma unroll
            for (int i = 0; i < 24; i++) {
                int gi = irow + i;
                float x = (gi < 128) ? ctxs[gi] : hist[gi - 128];
                s = fmaf(x, wreg[i], s);
            }
            cpart[(tid >> 6) * 64 + col] = s;
        }
        __syncthreads();
        if (tid < 64) {
            float s = bcs[tid];
#pragma unroll
            for (int p = 0; p < 8; p++) s += cpart[p*64 + tid];
            cvec[tid] = s;
        }
        __syncthreads();
        if (wid == 0) {
            float c0 = cvec[lane], c1 = cvec[lane + 32];
            float ss = c0*c0 + c1*c1;
#pragma unroll
            for (int off = 16; off > 0; off >>= 1) ss += __shfl_xor_sync(0xffffffffu, ss, off);
            if (lane == 0) scal[3] = 1.0f / fmaxf(sqrtf(ss), 1e-12f);
        }
        __syncthreads();
        if (tid < 64) cvec[tid] *= scal[3];
        __syncthreads();

        float sx = 0.f, sy = 0.f;
        if (tid < NCACHE / 2) {
            const float* ep = embc + 2 * tid;
#pragma unroll 8
            for (int k = 0; k < 64; k++) {
                float2 v = *reinterpret_cast<const float2*>(ep + k * NCACHE);
                float ck = cvec[k];
                sx = fmaf(v.x, ck, sx); sy = fmaf(v.y, ck, sy);
            }
        } else {
            const float* ep = embT + rank * RPC + 2 * tid;
#pragma unroll 16
            for (int k = 0; k < 64; k++) {
                float2 v = *reinterpret_cast<const float2*>(ep + (size_t)k * NRc);
                float ck = cvec[k];
                sx = fmaf(v.x, ck, sx); sy = fmaf(v.y, ck, sy);
            }
        }
        float e0 = expf(sx), e1 = expf(sy);
        float t2 = e0 + e1;

        float incl = t2;
#pragma unroll
        for (int off = 1; off < 32; off <<= 1) {
            float n = __shfl_up_sync(0xffffffffu, incl, off);
            if (lane >= off) incl += n;
        }
        if (lane == 31) wred[wid] = incl;
        __syncthreads();
        if (tid == 0) {
            float s = 0.0f;
#pragma unroll
            for (int w = 0; w < 16; w++) { float v = wred[w]; wexc[w] = s; s += v; }
            scal[4] = s;
        }
        __syncthreads();
        float S_local  = scal[4];
        float excl_thr = wexc[wid] + (incl - t2);

        if (tid < CL) st_async_b32(slotS, mbarS_a, (uint32_t)tid, __float_as_uint(S_local));
        mbar_wait_cluster(mbarS_a, par);
        float S_tot = 0.0f, pre = 0.0f;
#pragma unroll
        for (int r = 0; r < CL; r++) {
            float v = exchS[(step & 1) * 4 + r];
            if (r < rank) pre += v;
            S_tot += v;
        }

        float T = rand_vals[b * Ac + step] * S_tot;
        float base = pre + excl_thr;
        int cand = 0x7fffffff;
        int gr = rank * RPC + tid * 2;
        if      (base + e0 > T) cand = gr;
        else if (base + t2 > T) cand = gr + 1;
        if (cand != 0x7fffffff) atomicMin(seli, cand);
        __syncthreads();
        int lc = seli[0];
        if (tid < CL) st_async_b32(slotC, mbarC_a, (uint32_t)tid, (uint32_t)lc);
        mbar_wait_cluster(mbarC_a, par);
        int sel = 0x7fffffff;
#pragma unroll
        for (int r = 0; r < CL; r++) sel = min(sel, exchC[(step & 1) * 4 + r]);
        if (sel == 0x7fffffff) sel = 0;

        if (tid < 64) cur[tid] = embT[(size_t)tid * NRc + sel];
        __syncthreads();
        if (wid == 0) {
            float d = cur[lane] * cvec[lane] + cur[lane + 32] * cvec[lane + 32];
#pragma unroll
            for (int off = 16; off > 0; off >>= 1) d += __shfl_xor_sync(0xffffffffu, d, off);
            if (lane == 0) scal[0] += d - logf(S_tot);
        }
        if (rank == 0 && tid == 0) out[b * Ac + step] = (float)sel;
        __syncthreads();
    }

    if (rank == 0 && tid == 0) out[Bc*Ac + b] = scal[0];
    if (rank == 0 && tid < 64) out[Bc*Ac + Bc + b*Hc + tid] = hist[tid];
    CLUSTER_SYNC();
}

// ---------------- launcher ----------------
extern "C" void kernel_launch(void* const* d_in, const int* in_sizes, int n_in,
                              void* d_out, int out_size) {
    const float* roles     = (const float*)d_in[0];
    const float* contexts  = (const float*)d_in[1];
    const float* eps       = (const float*)d_in[2];
    const float* rand_vals = (const float*)d_in[3];
    const float* W1  = (const float*)d_in[5];
    const float* b1  = (const float*)d_in[6];
    const float* W21 = (const float*)d_in[7];
    const float* b21 = (const float*)d_in[8];
    const float* W22 = (const float*)d_in[9];
    const float* b22 = (const float*)d_in[10];
    const float* W3  = (const float*)d_in[11];
    const float* b3  = (const float*)d_in[12];
    const float* W4  = (const float*)d_in[13];
    const float* b4  = (const float*)d_in[14];
    const float* Wc  = (const float*)d_in[15];
    const float* bc  = (const float*)d_in[16];
    const float* init_emb = (const float*)d_in[17];
    float* out = (float*)d_out;

    const int vae_smem  = VAE_SMEM_FLOATS  * (int)sizeof(float);
    const int scan_smem = SCAN_SMEM_FLOATS * (int)sizeof(float);
    cudaFuncSetAttribute(vae_kernel,  cudaFuncAttributeMaxDynamicSharedMemorySize, vae_smem);
    cudaFuncSetAttribute(scan_kernel, cudaFuncAttributeMaxDynamicSharedMemorySize, scan_smem);

    zero_kernel<<<1, 32>>>();
    vae_kernel<<<MTOT / 128, 256, vae_smem>>>(roles, eps, W1, b1, W21, b21,
                                              W22, b22, W3, b3, W4, b4);
    scan_kernel<<<Bc * CL, STH, scan_smem>>>(contexts, rand_vals, Wc, bc,
                                             init_emb, out);
}

// round 11
// speedup vs baseline: 1.4752x; 1.0370x over previous
#include <cuda_runtime.h>
#include <math.h>
#include <stdint.h>

// ---------------- problem constants ----------------
#define Bc   32
#define NRc  4096
#define DIN  384
#define DCTX 128
#define Hc   64
#define Ac   16
#define MTOT (Bc * NRc)

#define LOG_VAR2_C  (-4.6051701859880914f)
#define INV_VAR2_C  (100.0f)
#define STD2_C      (0.1f)

// ---------------- device scratch (zero-initialized at module load; scan re-zeros
// g_mse/g_kld at end of every launch so each launch starts from zeros) ----------
__device__ float g_embT[(size_t)Bc * Hc * NRc];   // [b][k][n]
__device__ float g_mse[Bc];
__device__ float g_kld[Bc];

// ---------------- tf32 helpers ----------------
__device__ __forceinline__ float tf32r(float x) {
    uint32_t u; asm("cvt.rna.tf32.f32 %0, %1;" : "=r"(u) : "f"(x));
    return __uint_as_float(u);
}
__device__ __forceinline__ void mma_tf32(float c[4], const uint32_t a[4],
                                         uint32_t b0, uint32_t b1) {
    asm volatile("mma.sync.aligned.m16n8k8.row.col.f32.tf32.tf32.f32 "
        "{%0,%1,%2,%3}, {%4,%5,%6,%7}, {%8,%9}, {%0,%1,%2,%3};"
        : "+f"(c[0]), "+f"(c[1]), "+f"(c[2]), "+f"(c[3])
        : "r"(a[0]), "r"(a[1]), "r"(a[2]), "r"(a[3]), "r"(b0), "r"(b1));
}

#define WSP 68   // conflict-free row stride (floats)

// ---------------- fused VAE kernel ----------------
#define VAE_SMEM_FLOATS (2048 + 1024 + 8320 + 64*WSP + 64 + 128)

__global__ __launch_bounds__(256, 2)
void vae_kernel(const float* __restrict__ roles, const float* __restrict__ eps,
                const float* __restrict__ W1,  const float* __restrict__ b1,
                const float* __restrict__ W21, const float* __restrict__ b21,
                const float* __restrict__ W22, const float* __restrict__ b22,
                const float* __restrict__ W3,  const float* __restrict__ b3,
                const float* __restrict__ W4,  const float* __restrict__ b4)
{
    extern __shared__ float sm[];
    float* As  = sm;                 // 16*128
    float* Bs  = As + 2048;          // 16*64
    float* Hs  = Bs + 1024;          // 128*65
    float* Ws  = Hs + 8320;          // 64*WSP
    float* red = Ws + 64*WSP;        // 64
    float* rns = red + 64;           // 128

    const int tid  = threadIdx.x;
    const int tcol = tid & 15;
    const int trow = tid >> 4;
    const int row0 = blockIdx.x * 128;
    const int b    = row0 >> 12;

    float acc[8][4];

    // ================= GEMM1: h = relu(roles @ W1 + b1)  [fp32, prefetched] =====
#pragma unroll
    for (int i = 0; i < 8; i++)
#pragma unroll
        for (int j = 0; j < 4; j++) acc[i][j] = 0.0f;

    const int am0 = tid >> 2;
    const int ak0 = (tid & 3) * 4;
    const int am1 = (tid + 256) >> 2;
    const int ak1 = ((tid + 256) & 3) * 4;
    const int bk  = tid >> 4;
    const int bj4 = (tid & 15) * 4;

    float4 va0, va1, vb;
    va0 = *reinterpret_cast<const float4*>(roles + (size_t)(row0 + am0) * DIN + ak0);
    va1 = *reinterpret_cast<const float4*>(roles + (size_t)(row0 + am1) * DIN + ak1);
    vb  = *reinterpret_cast<const float4*>(W1 + (size_t)bk * Hc + bj4);

    for (int t = 0; t < 24; t++) {
        As[(ak0 + 0) * 128 + am0] = va0.x;
        As[(ak0 + 1) * 128 + am0] = va0.y;
        As[(ak0 + 2) * 128 + am0] = va0.z;
        As[(ak0 + 3) * 128 + am0] = va0.w;
        As[(ak1 + 0) * 128 + am1] = va1.x;
        As[(ak1 + 1) * 128 + am1] = va1.y;
        As[(ak1 + 2) * 128 + am1] = va1.z;
        As[(ak1 + 3) * 128 + am1] = va1.w;
        *reinterpret_cast<float4*>(&Bs[bk * 64 + bj4]) = vb;
        __syncthreads();

        if (t + 1 < 24) {
            const int kt = (t + 1) * 16;
            va0 = *reinterpret_cast<const float4*>(
                roles + (size_t)(row0 + am0) * DIN + kt + ak0);
            va1 = *reinterpret_cast<const float4*>(
                roles + (size_t)(row0 + am1) * DIN + kt + ak1);
            vb  = *reinterpret_cast<const float4*>(
                W1 + (size_t)(kt + bk) * Hc + bj4);
        }

#pragma unroll
        for (int k = 0; k < 16; k++) {
            float a[8];
            *reinterpret_cast<float4*>(&a[0]) = *reinterpret_cast<float4*>(&As[k*128 + trow*8]);
            *reinterpret_cast<float4*>(&a[4]) = *reinterpret_cast<float4*>(&As[k*128 + trow*8 + 4]);
            float4 bb = *reinterpret_cast<float4*>(&Bs[k*64 + tcol*4]);
#pragma unroll
            for (int i = 0; i < 8; i++) {
                acc[i][0] += a[i] * bb.x;
                acc[i][1] += a[i] * bb.y;
                acc[i][2] += a[i] * bb.z;
                acc[i][3] += a[i] * bb.w;
            }
        }
        __syncthreads();
    }
    {
        float4 bv = *reinterpret_cast<const float4*>(b1 + tcol * 4);
#pragma unroll
        for (int i = 0; i < 8; i++) {
            int r = trow * 8 + i;
            Hs[r*65 + tcol*4 + 0] = fmaxf(acc[i][0] + bv.x, 0.0f);
            Hs[r*65 + tcol*4 + 1] = fmaxf(acc[i][1] + bv.y, 0.0f);
            Hs[r*65 + tcol*4 + 2] = fmaxf(acc[i][2] + bv.z, 0.0f);
            Hs[r*65 + tcol*4 + 3] = fmaxf(acc[i][3] + bv.w, 0.0f);
        }
    }
    for (int t = tid; t < 1024; t += 256)
        *reinterpret_cast<float4*>(&Ws[t*4]) = *reinterpret_cast<const float4*>(W22 + t*4);
    __syncthreads();

    float kacc = 0.0f;
    float sreg[8][4];

    // prefetch W21 during W22 GEMM (stored after the GEMM completes)
    float4 w21p[4];
#pragma unroll
    for (int q = 0; q < 4; q++)
        w21p[q] = *reinterpret_cast<const float4*>(W21 + (size_t)(tid + q*256) * 4);

    // ================= log_var = h@W22 + b22  [fp32] =================
#pragma unroll
    for (int i = 0; i < 8; i++)
#pragma unroll
        for (int j = 0; j < 4; j++) acc[i][j] = 0.0f;
#pragma unroll 8
    for (int k = 0; k < 64; k++) {
        float a[8];
#pragma unroll
        for (int i = 0; i < 8; i++) a[i] = Hs[(trow*8 + i)*65 + k];
        float4 bb = *reinterpret_cast<float4*>(&Ws[k*64 + tcol*4]);
#pragma unroll
        for (int i = 0; i < 8; i++) {
            acc[i][0] += a[i]*bb.x; acc[i][1] += a[i]*bb.y;
            acc[i][2] += a[i]*bb.z; acc[i][3] += a[i]*bb.w;
        }
    }
    {
        float4 bv = *reinterpret_cast<const float4*>(b22 + tcol * 4);
#pragma unroll
        for (int i = 0; i < 8; i++) {
            float bvv[4] = {bv.x, bv.y, bv.z, bv.w};
#pragma unroll
            for (int j = 0; j < 4; j++) {
                float lv = acc[i][j] + bvv[j];
                float ex = expf(lv);
                kacc += (1.0f - LOG_VAR2_C + lv - ex * INV_VAR2_C);
                sreg[i][j] = expf(0.5f * lv) * STD2_C;
            }
        }
    }
    __syncthreads();
#pragma unroll
    for (int q = 0; q < 4; q++)
        *reinterpret_cast<float4*>(&Ws[(tid + q*256) * 4]) = w21p[q];
    __syncthreads();

    // ================= mu = h@W21 + b21 ; z = mu + eps*s  [fp32] =================
#pragma unroll
    for (int i = 0; i < 8; i++)
#pragma unroll
        for (int j = 0; j < 4; j++) acc[i][j] = 0.0f;
#pragma unroll 8
    for (int k = 0; k < 64; k++) {
        float a[8];
#pragma unroll
        for (int i = 0; i < 8; i++) a[i] = Hs[(trow*8 + i)*65 + k];
        float4 bb = *reinterpret_cast<float4*>(&Ws[k*64 + tcol*4]);
#pragma unroll
        for (int i = 0; i < 8; i++) {
            acc[i][0] += a[i]*bb.x; acc[i][1] += a[i]*bb.y;
            acc[i][2] += a[i]*bb.z; acc[i][3] += a[i]*bb.w;
        }
    }
    {
        float4 bv = *reinterpret_cast<const float4*>(b21 + tcol * 4);
        float bvv[4] = {bv.x, bv.y, bv.z, bv.w};
#pragma unroll
        for (int i = 0; i < 8; i++) {
            float4 ev = *reinterpret_cast<const float4*>(
                eps + (size_t)(row0 + trow*8 + i) * Hc + tcol * 4);
            float evv[4] = {ev.x, ev.y, ev.z, ev.w};
#pragma unroll
            for (int j = 0; j < 4; j++) {
                float mu = acc[i][j] + bvv[j];
                kacc -= mu * mu * INV_VAR2_C;
                acc[i][j] = mu + evv[j] * sreg[i][j];
            }
        }
    }
    __syncthreads();
    // z (fp32) -> Hs ; stage Ws = permuted tf32(W3)
#pragma unroll
    for (int i = 0; i < 8; i++) {
        int r = trow * 8 + i;
        Hs[r*65 + tcol*4 + 0] = acc[i][0];
        Hs[r*65 + tcol*4 + 1] = acc[i][1];
        Hs[r*65 + tcol*4 + 2] = acc[i][2];
        Hs[r*65 + tcol*4 + 3] = acc[i][3];
    }
    for (int t = tid; t < 4096; t += 256) {
        int k = t >> 6, n = t & 63;
        Ws[k*WSP + ((n & 7) << 3) + (n >> 3)] = tf32r(W3[t]);
    }
    __syncthreads();

    // ================= role_emb = l2norm(z), stored transposed =================
    if (tid < 128) {
        float ss = 0.0f;
#pragma unroll
        for (int k = 0; k < 64; k++) { float v = Hs[tid*65 + k]; ss += v * v; }
        rns[tid] = 1.0f / fmaxf(sqrtf(ss), 1e-12f);
    }
    __syncthreads();
    {
        const int nloc0 = row0 & (NRc - 1);
        for (int t = tid; t < 128 * 64; t += 256) {
            int k = t >> 7;
            int r = t & 127;
            g_embT[((size_t)b * Hc + k) * NRc + nloc0 + r] = Hs[r*65 + k] * rns[r];
        }
    }
    __syncthreads();
    for (int t = tid; t < 8192; t += 256) {
        int r = t >> 6, k = t & 63;
        Hs[r*65 + k] = tf32r(Hs[r*65 + k]);
    }
    __syncthreads();

    // ================= tf32 HMMA path: g = relu(z@W3+b3); mse(g@W4+b4) ========
    const int wid  = tid >> 5;
    const int lane = tid & 31;
    const int gid  = lane >> 2;
    const int tig  = lane & 3;
    const int mrow = wid * 16;

    uint32_t afr[8][4];
#pragma unroll
    for (int kt = 0; kt < 8; kt++) {
        int k0 = kt * 8;
        afr[kt][0] = __float_as_uint(Hs[(mrow+gid  )*65 + k0+tig  ]);
        afr[kt][1] = __float_as_uint(Hs[(mrow+gid+8)*65 + k0+tig  ]);
        afr[kt][2] = __float_as_uint(Hs[(mrow+gid  )*65 + k0+tig+4]);
        afr[kt][3] = __float_as_uint(Hs[(mrow+gid+8)*65 + k0+tig+4]);
    }
    float cfr[8][4];
#pragma unroll
    for (int nt = 0; nt < 8; nt++)
#pragma unroll
        for (int j = 0; j < 4; j++) cfr[nt][j] = 0.0f;
#pragma unroll
    for (int kt = 0; kt < 8; kt++) {
        const float4* p0 = reinterpret_cast<const float4*>(&Ws[(kt*8+tig  )*WSP + gid*8]);
        const float4* p1 = reinterpret_cast<const float4*>(&Ws[(kt*8+tig+4)*WSP + gid*8]);
        float4 b0a = p0[0], b0b = p0[1];
        float4 b1a = p1[0], b1b = p1[1];
        mma_tf32(cfr[0], afr[kt], __float_as_uint(b0a.x), __float_as_uint(b1a.x));
        mma_tf32(cfr[1], afr[kt], __float_as_uint(b0a.y), __float_as_uint(b1a.y));
        mma_tf32(cfr[2], afr[kt], __float_as_uint(b0a.z), __float_as_uint(b1a.z));
        mma_tf32(cfr[3], afr[kt], __float_as_uint(b0a.w), __float_as_uint(b1a.w));
        mma_tf32(cfr[4], afr[kt], __float_as_uint(b0b.x), __float_as_uint(b1b.x));
        mma_tf32(cfr[5], afr[kt], __float_as_uint(b0b.y), __float_as_uint(b1b.y));
        mma_tf32(cfr[6], afr[kt], __float_as_uint(b0b.z), __float_as_uint(b1b.z));
        mma_tf32(cfr[7], afr[kt], __float_as_uint(b0b.w), __float_as_uint(b1b.w));
    }
    __syncthreads();
#pragma unroll
    for (int nt = 0; nt < 8; nt++) {
        int col = nt*8 + 2*tig;
        float2 b3v = *reinterpret_cast<const float2*>(b3 + col);
        Hs[(mrow+gid  )*65 + col    ] = tf32r(fmaxf(cfr[nt][0] + b3v.x, 0.0f));
        Hs[(mrow+gid  )*65 + col + 1] = tf32r(fmaxf(cfr[nt][1] + b3v.y, 0.0f));
        Hs[(mrow+gid+8)*65 + col    ] = tf32r(fmaxf(cfr[nt][2] + b3v.x, 0.0f));
        Hs[(mrow+gid+8)*65 + col + 1] = tf32r(fmaxf(cfr[nt][3] + b3v.y, 0.0f));
    }
    __syncthreads();
#pragma unroll
    for (int kt = 0; kt < 8; kt++) {
        int k0 = kt * 8;
        afr[kt][0] = __float_as_uint(Hs[(mrow+gid  )*65 + k0+tig  ]);
        afr[kt][1] = __float_as_uint(Hs[(mrow+gid+8)*65 + k0+tig  ]);
        afr[kt][2] = __float_as_uint(Hs[(mrow+gid  )*65 + k0+tig+4]);
        afr[kt][3] = __float_as_uint(Hs[(mrow+gid+8)*65 + k0+tig+4]);
    }

    // W4 chunk staging coords: thread t owns 16 consecutive floats of each chunk
    const int sk = tid >> 2;                 // W4 k-row (0..63)
    const int sn = (tid & 3) * 16;           // chunk-local col start
    float4 wpre[4];
#pragma unroll
    for (int q = 0; q < 4; q++)
        wpre[q] = *reinterpret_cast<const float4*>(
            W4 + (size_t)sk * DIN + sn + q * 4);   // chunk 0

    float msacc = 0.0f;
    for (int ch = 0; ch < 6; ch++) {
        __syncthreads();   // prev chunk's Ws reads done
        {
            const float* wf = reinterpret_cast<const float*>(wpre);
#pragma unroll
            for (int j = 0; j < 16; j++) {
                int n = sn + j;
                Ws[sk*WSP + ((n & 7) << 3) + (n >> 3)] = tf32r(wf[j]);
            }
        }
        __syncthreads();
        // prefetch next chunk during compute
        if (ch + 1 < 6) {
#pragma unroll
            for (int q = 0; q < 4; q++)
                wpre[q] = *reinterpret_cast<const float4*>(
                    W4 + (size_t)sk * DIN + (ch + 1) * 64 + sn + q * 4);
        }
        float cf[8][4];
#pragma unroll
        for (int nt = 0; nt < 8; nt++)
#pragma unroll
            for (int j = 0; j < 4; j++) cf[nt][j] = 0.0f;
#pragma unroll
        for (int kt = 0; kt < 8; kt++) {
            const float4* p0 = reinterpret_cast<const float4*>(&Ws[(kt*8+tig  )*WSP + gid*8]);
            const float4* p1 = reinterpret_cast<const float4*>(&Ws[(kt*8+tig+4)*WSP + gid*8]);
            float4 b0a = p0[0], b0b = p0[1];
            float4 b1a = p1[0], b1b = p1[1];
            mma_tf32(cf[0], afr[kt], __float_as_uint(b0a.x), __float_as_uint(b1a.x));
            mma_tf32(cf[1], afr[kt], __float_as_uint(b0a.y), __float_as_uint(b1a.y));
            mma_tf32(cf[2], afr[kt], __float_as_uint(b0a.z), __float_as_uint(b1a.z));
            mma_tf32(cf[3], afr[kt], __float_as_uint(b0a.w), __float_as_uint(b1a.w));
            mma_tf32(cf[4], afr[kt], __float_as_uint(b0b.x), __float_as_uint(b1b.x));
            mma_tf32(cf[5], afr[kt], __float_as_uint(b0b.y), __float_as_uint(b1b.y));
            mma_tf32(cf[6], afr[kt], __float_as_uint(b0b.z), __float_as_uint(b1b.z));
            mma_tf32(cf[7], afr[kt], __float_as_uint(b0b.w), __float_as_uint(b1b.w));
        }
#pragma unroll
        for (int nt = 0; nt < 8; nt++) {
            int col = ch*64 + nt*8 + 2*tig;
            float2 b4v = *reinterpret_cast<const float2*>(b4 + col);
            float2 r0v = *reinterpret_cast<const float2*>(
                roles + (size_t)(row0 + mrow + gid    ) * DIN + col);
            float2 r1v = *reinterpret_cast<const float2*>(
                roles + (size_t)(row0 + mrow + gid + 8) * DIN + col);
            float d;
            d = cf[nt][0] + b4v.x - r0v.x; msacc += d*d;
            d = cf[nt][1] + b4v.y - r0v.y; msacc += d*d;
            d = cf[nt][2] + b4v.x - r1v.x; msacc += d*d;
            d = cf[nt][3] + b4v.y - r1v.y; msacc += d*d;
        }
    }

    // ================= block reduce kld / mse =================
    float ks = kacc, ms = msacc;
#pragma unroll
    for (int off = 16; off > 0; off >>= 1) {
        ks += __shfl_xor_sync(0xffffffffu, ks, off);
        ms += __shfl_xor_sync(0xffffffffu, ms, off);
    }
    __syncthreads();
    if ((tid & 31) == 0) { red[tid >> 5] = ks; red[8 + (tid >> 5)] = ms; }
    __syncthreads();
    if (tid == 0) {
        float kt = 0.0f, mt = 0.0f;
#pragma unroll
        for (int w = 0; w < 8; w++) { kt += red[w]; mt += red[8 + w]; }
        atomicAdd(&g_kld[b], kt);
        atomicAdd(&g_mse[b], mt);
    }
}

// ---------------- cluster / mbarrier helpers ----------------
__device__ __forceinline__ uint32_t s2u(const void* p) {
    uint32_t a;
    asm("{ .reg .u64 t; cvta.to.shared.u64 t, %1; cvt.u32.u64 %0, t; }" : "=r"(a) : "l"(p));
    return a;
}
__device__ __forceinline__ void mbar_init(uint32_t mbar, uint32_t cnt) {
    asm volatile("mbarrier.init.shared.b64 [%0], %1;" :: "r"(mbar), "r"(cnt) : "memory");
}
__device__ __forceinline__ void mbar_expect_tx(uint32_t mbar, uint32_t bytes) {
    asm volatile("mbarrier.arrive.expect_tx.shared.b64 _, [%0], %1;"
                 :: "r"(mbar), "r"(bytes) : "memory");
}
__device__ __forceinline__ void st_async_b32(uint32_t slot, uint32_t mbar,
                                             uint32_t peer, uint32_t val) {
    uint32_t rs, rb;
    asm("mapa.shared::cluster.u32 %0, %1, %2;" : "=r"(rs) : "r"(slot), "r"(peer));
    asm("mapa.shared::cluster.u32 %0, %1, %2;" : "=r"(rb) : "r"(mbar), "r"(peer));
    asm volatile("st.async.shared::cluster.mbarrier::complete_tx::bytes.b32 [%0], %1, [%2];"
                 :: "r"(rs), "r"(val), "r"(rb) : "memory");
}
__device__ __forceinline__ void mbar_wait_cluster(uint32_t mbar, uint32_t parity) {
    uint32_t done;
    asm volatile("{\n\t.reg .pred p;\n\t"
        "mbarrier.try_wait.parity.acquire.cluster.shared::cta.b64 p, [%1], %2;\n\t"
        "selp.b32 %0, 1, 0, p;\n\t}"
        : "=r"(done) : "r"(mbar), "r"(parity) : "memory");
    while (!done) {
        asm volatile("{\n\t.reg .pred p;\n\t"
            "mbarrier.try_wait.parity.acquire.cluster.shared::cta.b64 p, [%1], %2, 0x989680;\n\t"
            "selp.b32 %0, 1, 0, p;\n\t}"
            : "=r"(done) : "r"(mbar), "r"(parity) : "memory");
    }
}
#define CLUSTER_SYNC() do { \
    asm volatile("barrier.cluster.arrive.aligned;" ::: "memory"); \
    asm volatile("barrier.cluster.wait.aligned;"   ::: "memory"); } while (0)

// ---------------- cluster-parallel selection scan (+ finalize + re-zero) -------
#define CL 4
#define STH 512
#define RPC (NRc / CL)
#define NCACHE 768
#define SCAN_SMEM_FLOATS (1024 + 64*NCACHE)

__global__ __launch_bounds__(STH, 1) __cluster_dims__(CL, 1, 1)
void scan_kernel(const float* __restrict__ contexts, const float* __restrict__ rand_vals,
                 const float* __restrict__ Wc, const float* __restrict__ bc,
                 const float* __restrict__ init_emb, float* __restrict__ out)
{
    extern __shared__ float sm[];
    unsigned long long* mbar = (unsigned long long*)sm;
    float* exchS = sm + 4;
    int*   exchC = (int*)(sm + 12);
    int*   seli  = (int*)(sm + 20);
    float* scal  = sm + 21;
    float* wred  = sm + 28;
    float* wexc  = sm + 44;
    float* ctxs  = sm + 60;
    float* bcs   = sm + 188;
    float* hist  = sm + 252;
    float* cur   = sm + 316;
    float* tmp   = sm + 380;
    float* cvec  = sm + 444;
    float* cpart = sm + 508;
    float* embc  = sm + 1024;

    const int b    = blockIdx.x >> 2;
    const int rank = blockIdx.x & 3;
    const int tid  = threadIdx.x;
    const int lane = tid & 31;
    const int wid  = tid >> 5;

    // folded finalize: vae_loss (g_mse/g_kld complete at the kernel boundary)
    if (blockIdx.x == 0 && tid == 0) {
        float v = 0.0f;
        for (int bb = 0; bb < Bc; bb++) {
            float mse = g_mse[bb] * (1.0f / ((float)NRc * (float)DIN));
            float kld = (-0.5f / ((float)NRc * (float)Hc)) * g_kld[bb];
            v += mse + kld;
        }
        out[Bc*Ac + Bc + Bc*Hc] = v / (float)Bc;
        // re-zero accumulators for the next launch (graph replays); first launch
        // sees module-load zero-init, so every launch starts identically.
        for (int bb = 0; bb < Bc; bb++) { g_mse[bb] = 0.0f; g_kld[bb] = 0.0f; }
    }

    const uint32_t mbarS_a = s2u(&mbar[0]);
    const uint32_t mbarC_a = s2u(&mbar[1]);

    const float* embT = g_embT + (size_t)b * Hc * NRc;

    const int col  = tid & 63;
    const int irow = (tid >> 6) * 24;
    float wreg[24];
#pragma unroll
    for (int i = 0; i < 24; i++) wreg[i] = Wc[(size_t)(irow + i) * 64 + col];

    for (int t = tid; t < 64 * NCACHE / 4; t += STH) {
        int k  = t / (NCACHE / 4);
        int n4 = (t % (NCACHE / 4)) * 4;
        *reinterpret_cast<float4*>(&embc[k * NCACHE + n4]) =
            *reinterpret_cast<const float4*>(embT + (size_t)k * NRc + rank * RPC + n4);
    }
    if (tid < 128) ctxs[tid] = contexts[b * DCTX + tid];
    if (tid < 64)  { bcs[tid] = bc[tid]; float iv = init_emb[tid]; hist[tid] = iv; cur[tid] = iv; }
    if (tid == 0)  {
        scal[0] = 0.0f;
        mbar_init(mbarS_a, 1);
        mbar_init(mbarC_a, 1);
    }
    __syncthreads();
    CLUSTER_SYNC();

    for (int step = 0; step < Ac; step++) {
        const uint32_t par = (uint32_t)(step & 1);
        const uint32_t slotS = s2u(&exchS[(step & 1) * 4 + rank]);
        const uint32_t slotC = s2u(&exchC[(step & 1) * 4 + rank]);

        if (tid == 0) {
            mbar_expect_tx(mbarS_a, 16);
            mbar_expect_tx(mbarC_a, 16);
            seli[0] = 0x7fffffff;
        }
        if (tid < 64) tmp[tid] = hist[tid] + cur[tid];
        __syncthreads();
        if (wid == 0) {
            float x0 = tmp[lane], x1 = tmp[lane + 32];
            float s = x0 + x1;
#pragma unroll
            for (int off = 16; off > 0; off >>= 1) s += __shfl_xor_sync(0xffffffffu, s, off);
            float mean = s * (1.0f / 64.0f);
            float d0 = x0 - mean, d1 = x1 - mean;
            float vs = d0*d0 + d1*d1;
#pragma unroll
            for (int off = 16; off > 0; off >>= 1) vs += __shfl_xor_sync(0xffffffffu, vs, off);
            if (lane == 0) {
                scal[1] = mean;
                scal[2] = 1.0f / sqrtf(vs * (1.0f / 64.0f) + 1e-5f);
            }
        }
        __syncthreads();
        if (tid < 64) hist[tid] = (tmp[tid] - scal[1]) * scal[2];
        __syncthreads();

        {
            float s = 0.0f;
#pragma unroll
            for (int i = 0; i < 24; i++) {
                int gi = irow + i;
                float x = (gi < 128) ? ctxs[gi] : hist[gi - 128];
                s = fmaf(x, wreg[i], s);
            }
            cpart[(tid >> 6) * 64 + col] = s;
        }
        __syncthreads();
        if (tid < 64) {
            float s = bcs[tid];
#pragma unroll
            for (int p = 0; p < 8; p++) s += cpart[p*64 + tid];
            cvec[tid] = s;
        }
        __syncthreads();
        if (wid == 0) {
            float c0 = cvec[lane], c1 = cvec[lane + 32];
            float ss = c0*c0 + c1*c1;
#pragma unroll
            for (int off = 16; off > 0; off >>= 1) ss += __shfl_xor_sync(0xffffffffu, ss, off);
            if (lane == 0) scal[3] = 1.0f / fmaxf(sqrtf(ss), 1e-12f);
        }
        __syncthreads();
        if (tid < 64) cvec[tid] *= scal[3];
        __syncthreads();

        float sx = 0.f, sy = 0.f;
        if (tid < NCACHE / 2) {
            const float* ep = embc + 2 * tid;
#pragma unroll 8
            for (int k = 0; k < 64; k++) {
                float2 v = *reinterpret_cast<const float2*>(ep + k * NCACHE);
                float ck = cvec[k];
                sx = fmaf(v.x, ck, sx); sy = fmaf(v.y, ck, sy);
            }
        } else {
            const float* ep = embT + rank * RPC + 2 * tid;
#pragma unroll 16
            for (int k = 0; k < 64; k++) {
                float2 v = *reinterpret_cast<const float2*>(ep + (size_t)k * NRc);
                float ck = cvec[k];
                sx = fmaf(v.x, ck, sx); sy = fmaf(v.y, ck, sy);
            }
        }
        float e0 = expf(sx), e1 = expf(sy);
        float t2 = e0 + e1;

        float incl = t2;
#pragma unroll
        for (int off = 1; off < 32; off <<= 1) {
            float n = __shfl_up_sync(0xffffffffu, incl, off);
            if (lane >= off) incl += n;
        }
        if (lane == 31) wred[wid] = incl;
        __syncthreads();
        if (tid == 0) {
            float s = 0.0f;
#pragma unroll
            for (int w = 0; w < 16; w++) { float v = wred[w]; wexc[w] = s; s += v; }
            scal[4] = s;
        }
        __syncthreads();
        float S_local  = scal[4];
        float excl_thr = wexc[wid] + (incl - t2);

        if (tid < CL) st_async_b32(slotS, mbarS_a, (uint32_t)tid, __float_as_uint(S_local));
        mbar_wait_cluster(mbarS_a, par);
        float S_tot = 0.0f, pre = 0.0f;
#pragma unroll
        for (int r = 0; r < CL; r++) {
            float v = exchS[(step & 1) * 4 + r];
            if (r < rank) pre += v;
            S_tot += v;
        }

        float T = rand_vals[b * Ac + step] * S_tot;
        float base = pre + excl_thr;
        int cand = 0x7fffffff;
        int gr = rank * RPC + tid * 2;
        if      (base + e0 > T) cand = gr;
        else if (base + t2 > T) cand = gr + 1;
        if (cand != 0x7fffffff) atomicMin(seli, cand);
        __syncthreads();
        int lc = seli[0];
        if (tid < CL) st_async_b32(slotC, mbarC_a, (uint32_t)tid, (uint32_t)lc);
        mbar_wait_cluster(mbarC_a, par);
        int sel = 0x7fffffff;
#pragma unroll
        for (int r = 0; r < CL; r++) sel = min(sel, exchC[(step & 1) * 4 + r]);
        if (sel == 0x7fffffff) sel = 0;

        if (tid < 64) cur[tid] = embT[(size_t)tid * NRc + sel];
        __syncthreads();
        if (wid == 0) {
            float d = cur[lane] * cvec[lane] + cur[lane + 32] * cvec[lane + 32];
#pragma unroll
            for (int off = 16; off > 0; off >>= 1) d += __shfl_xor_sync(0xffffffffu, d, off);
            if (lane == 0) scal[0] += d - logf(S_tot);
        }
        if (rank == 0 && tid == 0) out[b * Ac + step] = (float)sel;
        __syncthreads();
    }

    if (rank == 0 && tid == 0) out[Bc*Ac + b] = scal[0];
    if (rank == 0 && tid < 64) out[Bc*Ac + Bc + b*Hc + tid] = hist[tid];
    CLUSTER_SYNC();
}

// ---------------- launcher ----------------
extern "C" void kernel_launch(void* const* d_in, const int* in_sizes, int n_in,
                              void* d_out, int out_size) {
    const float* roles     = (const float*)d_in[0];
    const float* contexts  = (const float*)d_in[1];
    const float* eps       = (const float*)d_in[2];
    const float* rand_vals = (const float*)d_in[3];
    const float* W1  = (const float*)d_in[5];
    const float* b1  = (const float*)d_in[6];
    const float* W21 = (const float*)d_in[7];
    const float* b21 = (const float*)d_in[8];
    const float* W22 = (const float*)d_in[9];
    const float* b22 = (const float*)d_in[10];
    const float* W3  = (const float*)d_in[11];
    const float* b3  = (const float*)d_in[12];
    const float* W4  = (const float*)d_in[13];
    const float* b4  = (const float*)d_in[14];
    const float* Wc  = (const float*)d_in[15];
    const float* bc  = (const float*)d_in[16];
    const float* init_emb = (const float*)d_in[17];
    float* out = (float*)d_out;

    const int vae_smem  = VAE_SMEM_FLOATS  * (int)sizeof(float);
    const int scan_smem = SCAN_SMEM_FLOATS * (int)sizeof(float);
    cudaFuncSetAttribute(vae_kernel,  cudaFuncAttributeMaxDynamicSharedMemorySize, vae_smem);
    cudaFuncSetAttribute(scan_kernel, cudaFuncAttributeMaxDynamicSharedMemorySize, scan_smem);

    vae_kernel<<<MTOT / 128, 256, vae_smem>>>(roles, eps, W1, b1, W21, b21,
                                              W22, b22, W3, b3, W4, b4);
    scan_kernel<<<Bc * CL, STH, scan_smem>>>(contexts, rand_vals, Wc, bc,
                                             init_emb, out);
}

// round 12
// speedup vs baseline: 1.5056x; 1.0207x over previous
#include <cuda_runtime.h>
#include <math.h>
#include <stdint.h>

// ---------------- problem constants ----------------
#define Bc   32
#define NRc  4096
#define DIN  384
#define DCTX 128
#define Hc   64
#define Ac   16
#define MTOT (Bc * NRc)

#define LOG_VAR2_C  (-4.6051701859880914f)
#define INV_VAR2_C  (100.0f)
#define STD2_C      (0.1f)

// ---------------- device scratch (zero-init at module load; scan re-zeros
// g_mse/g_kld at end of every launch so each launch starts from zeros) ----------
__device__ float g_embT[(size_t)Bc * Hc * NRc];   // [b][k][n]
__device__ float g_mse[Bc];
__device__ float g_kld[Bc];

// ---------------- tf32 helpers ----------------
__device__ __forceinline__ float tf32r(float x) {
    uint32_t u; asm("cvt.rna.tf32.f32 %0, %1;" : "=r"(u) : "f"(x));
    return __uint_as_float(u);
}
__device__ __forceinline__ void mma_tf32(float c[4], const uint32_t a[4],
                                         uint32_t b0, uint32_t b1) {
    asm volatile("mma.sync.aligned.m16n8k8.row.col.f32.tf32.tf32.f32 "
        "{%0,%1,%2,%3}, {%4,%5,%6,%7}, {%8,%9}, {%0,%1,%2,%3};"
        : "+f"(c[0]), "+f"(c[1]), "+f"(c[2]), "+f"(c[3])
        : "r"(a[0]), "r"(a[1]), "r"(a[2]), "r"(a[3]), "r"(b0), "r"(b1));
}

#define WSP 68   // conflict-free row stride (floats)

// ---------------- fused VAE kernel ----------------
#define VAE_SMEM_FLOATS (2048 + 1024 + 8320 + 64*WSP + 64 + 128)

__global__ __launch_bounds__(256, 2)
void vae_kernel(const float* __restrict__ roles, const float* __restrict__ eps,
                const float* __restrict__ W1,  const float* __restrict__ b1,
                const float* __restrict__ W21, const float* __restrict__ b21,
                const float* __restrict__ W22, const float* __restrict__ b22,
                const float* __restrict__ W3,  const float* __restrict__ b3,
                const float* __restrict__ W4,  const float* __restrict__ b4)
{
    extern __shared__ float sm[];
    float* As  = sm;                 // 16*128
    float* Bs  = As + 2048;          // 16*64
    float* Hs  = Bs + 1024;          // 128*65
    float* Ws  = Hs + 8320;          // 64*WSP
    float* red = Ws + 64*WSP;        // 64
    float* rns = red + 64;           // 128

    const int tid  = threadIdx.x;
    const int tcol = tid & 15;
    const int trow = tid >> 4;
    const int row0 = blockIdx.x * 128;
    const int b    = row0 >> 12;

    float acc[8][4];

    // ================= GEMM1: h = relu(roles @ W1 + b1)  [fp32, prefetched] =====
#pragma unroll
    for (int i = 0; i < 8; i++)
#pragma unroll
        for (int j = 0; j < 4; j++) acc[i][j] = 0.0f;

    const int am0 = tid >> 2;
    const int ak0 = (tid & 3) * 4;
    const int am1 = (tid + 256) >> 2;
    const int ak1 = ((tid + 256) & 3) * 4;
    const int bk  = tid >> 4;
    const int bj4 = (tid & 15) * 4;

    float4 va0, va1, vb;
    va0 = *reinterpret_cast<const float4*>(roles + (size_t)(row0 + am0) * DIN + ak0);
    va1 = *reinterpret_cast<const float4*>(roles + (size_t)(row0 + am1) * DIN + ak1);
    vb  = *reinterpret_cast<const float4*>(W1 + (size_t)bk * Hc + bj4);

    for (int t = 0; t < 24; t++) {
        As[(ak0 + 0) * 128 + am0] = va0.x;
        As[(ak0 + 1) * 128 + am0] = va0.y;
        As[(ak0 + 2) * 128 + am0] = va0.z;
        As[(ak0 + 3) * 128 + am0] = va0.w;
        As[(ak1 + 0) * 128 + am1] = va1.x;
        As[(ak1 + 1) * 128 + am1] = va1.y;
        As[(ak1 + 2) * 128 + am1] = va1.z;
        As[(ak1 + 3) * 128 + am1] = va1.w;
        *reinterpret_cast<float4*>(&Bs[bk * 64 + bj4]) = vb;
        __syncthreads();

        if (t + 1 < 24) {
            const int kt = (t + 1) * 16;
            va0 = *reinterpret_cast<const float4*>(
                roles + (size_t)(row0 + am0) * DIN + kt + ak0);
            va1 = *reinterpret_cast<const float4*>(
                roles + (size_t)(row0 + am1) * DIN + kt + ak1);
            vb  = *reinterpret_cast<const float4*>(
                W1 + (size_t)(kt + bk) * Hc + bj4);
        }

#pragma unroll
        for (int k = 0; k < 16; k++) {
            float a[8];
            *reinterpret_cast<float4*>(&a[0]) = *reinterpret_cast<float4*>(&As[k*128 + trow*8]);
            *reinterpret_cast<float4*>(&a[4]) = *reinterpret_cast<float4*>(&As[k*128 + trow*8 + 4]);
            float4 bb = *reinterpret_cast<float4*>(&Bs[k*64 + tcol*4]);
#pragma unroll
            for (int i = 0; i < 8; i++) {
                acc[i][0] += a[i] * bb.x;
                acc[i][1] += a[i] * bb.y;
                acc[i][2] += a[i] * bb.z;
                acc[i][3] += a[i] * bb.w;
            }
        }
        __syncthreads();
    }
    {
        float4 bv = *reinterpret_cast<const float4*>(b1 + tcol * 4);
#pragma unroll
        for (int i = 0; i < 8; i++) {
            int r = trow * 8 + i;
            Hs[r*65 + tcol*4 + 0] = fmaxf(acc[i][0] + bv.x, 0.0f);
            Hs[r*65 + tcol*4 + 1] = fmaxf(acc[i][1] + bv.y, 0.0f);
            Hs[r*65 + tcol*4 + 2] = fmaxf(acc[i][2] + bv.z, 0.0f);
            Hs[r*65 + tcol*4 + 3] = fmaxf(acc[i][3] + bv.w, 0.0f);
        }
    }
    for (int t = tid; t < 1024; t += 256)
        *reinterpret_cast<float4*>(&Ws[t*4]) = *reinterpret_cast<const float4*>(W22 + t*4);
    __syncthreads();

    float kacc = 0.0f;
    float sreg[8][4];

    // prefetch W21 during W22 GEMM
    float4 w21p[4];
#pragma unroll
    for (int q = 0; q < 4; q++)
        w21p[q] = *reinterpret_cast<const float4*>(W21 + (size_t)(tid + q*256) * 4);

    // ================= log_var = h@W22 + b22  [fp32] =================
#pragma unroll
    for (int i = 0; i < 8; i++)
#pragma unroll
        for (int j = 0; j < 4; j++) acc[i][j] = 0.0f;
#pragma unroll 8
    for (int k = 0; k < 64; k++) {
        float a[8];
#pragma unroll
        for (int i = 0; i < 8; i++) a[i] = Hs[(trow*8 + i)*65 + k];
        float4 bb = *reinterpret_cast<float4*>(&Ws[k*64 + tcol*4]);
#pragma unroll
        for (int i = 0; i < 8; i++) {
            acc[i][0] += a[i]*bb.x; acc[i][1] += a[i]*bb.y;
            acc[i][2] += a[i]*bb.z; acc[i][3] += a[i]*bb.w;
        }
    }
    {
        float4 bv = *reinterpret_cast<const float4*>(b22 + tcol * 4);
#pragma unroll
        for (int i = 0; i < 8; i++) {
            float bvv[4] = {bv.x, bv.y, bv.z, bv.w};
#pragma unroll
            for (int j = 0; j < 4; j++) {
                float lv = acc[i][j] + bvv[j];
                float ex = expf(lv);
                kacc += (1.0f - LOG_VAR2_C + lv - ex * INV_VAR2_C);
                sreg[i][j] = expf(0.5f * lv) * STD2_C;
            }
        }
    }
    __syncthreads();
#pragma unroll
    for (int q = 0; q < 4; q++)
        *reinterpret_cast<float4*>(&Ws[(tid + q*256) * 4]) = w21p[q];
    __syncthreads();

    // ================= mu = h@W21 + b21 ; z = mu + eps*s  [fp32] =================
#pragma unroll
    for (int i = 0; i < 8; i++)
#pragma unroll
        for (int j = 0; j < 4; j++) acc[i][j] = 0.0f;
#pragma unroll 8
    for (int k = 0; k < 64; k++) {
        float a[8];
#pragma unroll
        for (int i = 0; i < 8; i++) a[i] = Hs[(trow*8 + i)*65 + k];
        float4 bb = *reinterpret_cast<float4*>(&Ws[k*64 + tcol*4]);
#pragma unroll
        for (int i = 0; i < 8; i++) {
            acc[i][0] += a[i]*bb.x; acc[i][1] += a[i]*bb.y;
            acc[i][2] += a[i]*bb.z; acc[i][3] += a[i]*bb.w;
        }
    }
    {
        float4 bv = *reinterpret_cast<const float4*>(b21 + tcol * 4);
        float bvv[4] = {bv.x, bv.y, bv.z, bv.w};
#pragma unroll
        for (int i = 0; i < 8; i++) {
            float4 ev = *reinterpret_cast<const float4*>(
                eps + (size_t)(row0 + trow*8 + i) * Hc + tcol * 4);
            float evv[4] = {ev.x, ev.y, ev.z, ev.w};
#pragma unroll
            for (int j = 0; j < 4; j++) {
                float mu = acc[i][j] + bvv[j];
                kacc -= mu * mu * INV_VAR2_C;
                acc[i][j] = mu + evv[j] * sreg[i][j];
            }
        }
    }
    __syncthreads();
    // z (fp32) -> Hs ; stage Ws = permuted tf32(W3)
#pragma unroll
    for (int i = 0; i < 8; i++) {
        int r = trow * 8 + i;
        Hs[r*65 + tcol*4 + 0] = acc[i][0];
        Hs[r*65 + tcol*4 + 1] = acc[i][1];
        Hs[r*65 + tcol*4 + 2] = acc[i][2];
        Hs[r*65 + tcol*4 + 3] = acc[i][3];
    }
    for (int t = tid; t < 4096; t += 256) {
        int k = t >> 6, n = t & 63;
        Ws[k*WSP + ((n & 7) << 3) + (n >> 3)] = tf32r(W3[t]);
    }
    __syncthreads();

    // ================= role_emb = l2norm(z), stored transposed =================
    if (tid < 128) {
        float ss = 0.0f;
#pragma unroll
        for (int k = 0; k < 64; k++) { float v = Hs[tid*65 + k]; ss += v * v; }
        rns[tid] = 1.0f / fmaxf(sqrtf(ss), 1e-12f);
    }
    __syncthreads();
    {
        const int nloc0 = row0 & (NRc - 1);
        for (int t = tid; t < 128 * 64; t += 256) {
            int k = t >> 7;
            int r = t & 127;
            g_embT[((size_t)b * Hc + k) * NRc + nloc0 + r] = Hs[r*65 + k] * rns[r];
        }
    }
    // NOTE: no z->tf32 smem pass; rounding happens in the fragment build below.
    // Hs(z) is unmodified after this point until the g write (guarded by the
    // sync after the W3 mma loop).

    // ================= tf32 HMMA path: g = relu(z@W3+b3); mse(g@W4+b4) ========
    const int wid  = tid >> 5;
    const int lane = tid & 31;
    const int gid  = lane >> 2;
    const int tig  = lane & 3;
    const int mrow = wid * 16;

    uint32_t afr[8][4];
#pragma unroll
    for (int kt = 0; kt < 8; kt++) {
        int k0 = kt * 8;
        afr[kt][0] = __float_as_uint(tf32r(Hs[(mrow+gid  )*65 + k0+tig  ]));
        afr[kt][1] = __float_as_uint(tf32r(Hs[(mrow+gid+8)*65 + k0+tig  ]));
        afr[kt][2] = __float_as_uint(tf32r(Hs[(mrow+gid  )*65 + k0+tig+4]));
        afr[kt][3] = __float_as_uint(tf32r(Hs[(mrow+gid+8)*65 + k0+tig+4]));
    }
    float cfr[8][4];
#pragma unroll
    for (int nt = 0; nt < 8; nt++)
#pragma unroll
        for (int j = 0; j < 4; j++) cfr[nt][j] = 0.0f;
#pragma unroll
    for (int kt = 0; kt < 8; kt++) {
        const float4* p0 = reinterpret_cast<const float4*>(&Ws[(kt*8+tig  )*WSP + gid*8]);
        const float4* p1 = reinterpret_cast<const float4*>(&Ws[(kt*8+tig+4)*WSP + gid*8]);
        float4 b0a = p0[0], b0b = p0[1];
        float4 b1a = p1[0], b1b = p1[1];
        mma_tf32(cfr[0], afr[kt], __float_as_uint(b0a.x), __float_as_uint(b1a.x));
        mma_tf32(cfr[1], afr[kt], __float_as_uint(b0a.y), __float_as_uint(b1a.y));
        mma_tf32(cfr[2], afr[kt], __float_as_uint(b0a.z), __float_as_uint(b1a.z));
        mma_tf32(cfr[3], afr[kt], __float_as_uint(b0a.w), __float_as_uint(b1a.w));
        mma_tf32(cfr[4], afr[kt], __float_as_uint(b0b.x), __float_as_uint(b1b.x));
        mma_tf32(cfr[5], afr[kt], __float_as_uint(b0b.y), __float_as_uint(b1b.y));
        mma_tf32(cfr[6], afr[kt], __float_as_uint(b0b.z), __float_as_uint(b1b.z));
        mma_tf32(cfr[7], afr[kt], __float_as_uint(b0b.w), __float_as_uint(b1b.w));
    }
    __syncthreads();   // all reads of Hs(z) / Ws(W3) / emb-store reads done
    // g = tf32(relu(c + b3)) -> Hs
#pragma unroll
    for (int nt = 0; nt < 8; nt++) {
        int col = nt*8 + 2*tig;
        float2 b3v = *reinterpret_cast<const float2*>(b3 + col);
        Hs[(mrow+gid  )*65 + col    ] = tf32r(fmaxf(cfr[nt][0] + b3v.x, 0.0f));
        Hs[(mrow+gid  )*65 + col + 1] = tf32r(fmaxf(cfr[nt][1] + b3v.y, 0.0f));
        Hs[(mrow+gid+8)*65 + col    ] = tf32r(fmaxf(cfr[nt][2] + b3v.x, 0.0f));
        Hs[(mrow+gid+8)*65 + col + 1] = tf32r(fmaxf(cfr[nt][3] + b3v.y, 0.0f));
    }
    __syncthreads();
#pragma unroll
    for (int kt = 0; kt < 8; kt++) {
        int k0 = kt * 8;
        afr[kt][0] = __float_as_uint(Hs[(mrow+gid  )*65 + k0+tig  ]);
        afr[kt][1] = __float_as_uint(Hs[(mrow+gid+8)*65 + k0+tig  ]);
        afr[kt][2] = __float_as_uint(Hs[(mrow+gid  )*65 + k0+tig+4]);
        afr[kt][3] = __float_as_uint(Hs[(mrow+gid+8)*65 + k0+tig+4]);
    }

    // W4 chunk staging: thread owns 16 consecutive floats; double-buffered
    const int sk = tid >> 2;
    const int sn = (tid & 3) * 16;
    float4 wpre[4];
#pragma unroll
    for (int q = 0; q < 4; q++)
        wpre[q] = *reinterpret_cast<const float4*>(
            W4 + (size_t)sk * DIN + sn + q * 4);

    float msacc = 0.0f;
    for (int ch = 0; ch < 6; ch++) {
        __syncthreads();
        {
            const float* wf = reinterpret_cast<const float*>(wpre);
#pragma unroll
            for (int j = 0; j < 16; j++) {
                int n = sn + j;
                Ws[sk*WSP + ((n & 7) << 3) + (n >> 3)] = tf32r(wf[j]);
            }
        }
        __syncthreads();
        if (ch + 1 < 6) {
#pragma unroll
            for (int q = 0; q < 4; q++)
                wpre[q] = *reinterpret_cast<const float4*>(
                    W4 + (size_t)sk * DIN + (ch + 1) * 64 + sn + q * 4);
        }
        float cf[8][4];
#pragma unroll
        for (int nt = 0; nt < 8; nt++)
#pragma unroll
            for (int j = 0; j < 4; j++) cf[nt][j] = 0.0f;
#pragma unroll
        for (int kt = 0; kt < 8; kt++) {
            const float4* p0 = reinterpret_cast<const float4*>(&Ws[(kt*8+tig  )*WSP + gid*8]);
            const float4* p1 = reinterpret_cast<const float4*>(&Ws[(kt*8+tig+4)*WSP + gid*8]);
            float4 b0a = p0[0], b0b = p0[1];
            float4 b1a = p1[0], b1b = p1[1];
            mma_tf32(cf[0], afr[kt], __float_as_uint(b0a.x), __float_as_uint(b1a.x));
            mma_tf32(cf[1], afr[kt], __float_as_uint(b0a.y), __float_as_uint(b1a.y));
            mma_tf32(cf[2], afr[kt], __float_as_uint(b0a.z), __float_as_uint(b1a.z));
            mma_tf32(cf[3], afr[kt], __float_as_uint(b0a.w), __float_as_uint(b1a.w));
            mma_tf32(cf[4], afr[kt], __float_as_uint(b0b.x), __float_as_uint(b1b.x));
            mma_tf32(cf[5], afr[kt], __float_as_uint(b0b.y), __float_as_uint(b1b.y));
            mma_tf32(cf[6], afr[kt], __float_as_uint(b0b.z), __float_as_uint(b1b.z));
            mma_tf32(cf[7], afr[kt], __float_as_uint(b0b.w), __float_as_uint(b1b.w));
        }
#pragma unroll
        for (int nt = 0; nt < 8; nt++) {
            int col = ch*64 + nt*8 + 2*tig;
            float2 b4v = *reinterpret_cast<const float2*>(b4 + col);
            float2 r0v = *reinterpret_cast<const float2*>(
                roles + (size_t)(row0 + mrow + gid    ) * DIN + col);
            float2 r1v = *reinterpret_cast<const float2*>(
                roles + (size_t)(row0 + mrow + gid + 8) * DIN + col);
            float d;
            d = cf[nt][0] + b4v.x - r0v.x; msacc += d*d;
            d = cf[nt][1] + b4v.y - r0v.y; msacc += d*d;
            d = cf[nt][2] + b4v.x - r1v.x; msacc += d*d;
            d = cf[nt][3] + b4v.y - r1v.y; msacc += d*d;
        }
    }

    // ================= block reduce kld / mse =================
    float ks = kacc, ms = msacc;
#pragma unroll
    for (int off = 16; off > 0; off >>= 1) {
        ks += __shfl_xor_sync(0xffffffffu, ks, off);
        ms += __shfl_xor_sync(0xffffffffu, ms, off);
    }
    __syncthreads();
    if ((tid & 31) == 0) { red[tid >> 5] = ks; red[8 + (tid >> 5)] = ms; }
    __syncthreads();
    if (tid == 0) {
        float kt = 0.0f, mt = 0.0f;
#pragma unroll
        for (int w = 0; w < 8; w++) { kt += red[w]; mt += red[8 + w]; }
        atomicAdd(&g_kld[b], kt);
        atomicAdd(&g_mse[b], mt);
    }
}

// ---------------- cluster / mbarrier helpers ----------------
__device__ __forceinline__ uint32_t s2u(const void* p) {
    uint32_t a;
    asm("{ .reg .u64 t; cvta.to.shared.u64 t, %1; cvt.u32.u64 %0, t; }" : "=r"(a) : "l"(p));
    return a;
}
__device__ __forceinline__ void mbar_init(uint32_t mbar, uint32_t cnt) {
    asm volatile("mbarrier.init.shared.b64 [%0], %1;" :: "r"(mbar), "r"(cnt) : "memory");
}
__device__ __forceinline__ void mbar_expect_tx(uint32_t mbar, uint32_t bytes) {
    asm volatile("mbarrier.arrive.expect_tx.shared.b64 _, [%0], %1;"
                 :: "r"(mbar), "r"(bytes) : "memory");
}
__device__ __forceinline__ void st_async_b32(uint32_t slot, uint32_t mbar,
                                             uint32_t peer, uint32_t val) {
    uint32_t rs, rb;
    asm("mapa.shared::cluster.u32 %0, %1, %2;" : "=r"(rs) : "r"(slot), "r"(peer));
    asm("mapa.shared::cluster.u32 %0, %1, %2;" : "=r"(rb) : "r"(mbar), "r"(peer));
    asm volatile("st.async.shared::cluster.mbarrier::complete_tx::bytes.b32 [%0], %1, [%2];"
                 :: "r"(rs), "r"(val), "r"(rb) : "memory");
}
__device__ __forceinline__ void mbar_wait_cluster(uint32_t mbar, uint32_t parity) {
    uint32_t done;
    asm volatile("{\n\t.reg .pred p;\n\t"
        "mbarrier.try_wait.parity.acquire.cluster.shared::cta.b64 p, [%1], %2;\n\t"
        "selp.b32 %0, 1, 0, p;\n\t}"
        : "=r"(done) : "r"(mbar), "r"(parity) : "memory");
    while (!done) {
        asm volatile("{\n\t.reg .pred p;\n\t"
            "mbarrier.try_wait.parity.acquire.cluster.shared::cta.b64 p, [%1], %2, 0x989680;\n\t"
            "selp.b32 %0, 1, 0, p;\n\t}"
            : "=r"(done) : "r"(mbar), "r"(parity) : "memory");
    }
}
#define CLUSTER_SYNC() do { \
    asm volatile("barrier.cluster.arrive.aligned;" ::: "memory"); \
    asm volatile("barrier.cluster.wait.aligned;"   ::: "memory"); } while (0)

// ---------------- cluster-parallel selection scan ----------------
#define CL 4
#define STH 512
#define RPC (NRc / CL)
#define NCACHE 768
#define SCAN_SMEM_FLOATS (1024 + 64*NCACHE)

__global__ __launch_bounds__(STH, 1) __cluster_dims__(CL, 1, 1)
void scan_kernel(const float* __restrict__ contexts, const float* __restrict__ rand_vals,
                 const float* __restrict__ Wc, const float* __restrict__ bc,
                 const float* __restrict__ init_emb, float* __restrict__ out)
{
    extern __shared__ float sm[];
    unsigned long long* mbar = (unsigned long long*)sm;
    float* exchS = sm + 4;
    int*   exchC = (int*)(sm + 12);
    int*   seli  = (int*)(sm + 20);
    float* scal  = sm + 21;
    float* wred  = sm + 28;
    float* wexc  = sm + 44;
    float* ctxs  = sm + 60;
    float* bcs   = sm + 188;
    float* hist  = sm + 252;
    float* cur   = sm + 316;
    float* tmp   = sm + 380;
    float* cvec  = sm + 444;
    float* cpart = sm + 508;
    float* embc  = sm + 1024;

    const int b    = blockIdx.x >> 2;
    const int rank = blockIdx.x & 3;
    const int tid  = threadIdx.x;
    const int lane = tid & 31;
    const int wid  = tid >> 5;

    // folded finalize: vae_loss (g_mse/g_kld complete at the kernel boundary)
    if (blockIdx.x == 0 && tid == 0) {
        float v = 0.0f;
        for (int bb = 0; bb < Bc; bb++) {
            float mse = g_mse[bb] * (1.0f / ((float)NRc * (float)DIN));
            float kld = (-0.5f / ((float)NRc * (float)Hc)) * g_kld[bb];
            v += mse + kld;
        }
        out[Bc*Ac + Bc + Bc*Hc] = v / (float)Bc;
        for (int bb = 0; bb < Bc; bb++) { g_mse[bb] = 0.0f; g_kld[bb] = 0.0f; }
    }

    const uint32_t mbarS_a = s2u(&mbar[0]);
    const uint32_t mbarC_a = s2u(&mbar[1]);

    const float* embT = g_embT + (size_t)b * Hc * NRc;

    const int col  = tid & 63;
    const int irow = (tid >> 6) * 24;
    float wreg[24];
#pragma unroll
    for (int i = 0; i < 24; i++) wreg[i] = Wc[(size_t)(irow + i) * 64 + col];

    for (int t = tid; t < 64 * NCACHE / 4; t += STH) {
        int k  = t / (NCACHE / 4);
        int n4 = (t % (NCACHE / 4)) * 4;
        *reinterpret_cast<float4*>(&embc[k * NCACHE + n4]) =
            *reinterpret_cast<const float4*>(embT + (size_t)k * NRc + rank * RPC + n4);
    }
    if (tid < 128) ctxs[tid] = contexts[b * DCTX + tid];
    if (tid < 64)  { bcs[tid] = bc[tid]; float iv = init_emb[tid]; hist[tid] = iv; cur[tid] = iv; }
    if (tid == 0)  {
        scal[0] = 0.0f;
        mbar_init(mbarS_a, 1);
        mbar_init(mbarC_a, 1);
    }
    __syncthreads();
    CLUSTER_SYNC();

    for (int step = 0; step < Ac; step++) {
        const uint32_t par = (uint32_t)(step & 1);
        const uint32_t slotS = s2u(&exchS[(step & 1) * 4 + rank]);
        const uint32_t slotC = s2u(&exchC[(step & 1) * 4 + rank]);

        if (tid == 0) {
            mbar_expect_tx(mbarS_a, 16);
            mbar_expect_tx(mbarC_a, 16);
            seli[0] = 0x7fffffff;
        }
        if (tid < 64) tmp[tid] = hist[tid] + cur[tid];
        __syncthreads();
        if (wid == 0) {
            float x0 = tmp[lane], x1 = tmp[lane + 32];
            float s = x0 + x1;
#pragma unroll
            for (int off = 16; off > 0; off >>= 1) s += __shfl_xor_sync(0xffffffffu, s, off);
            float mean = s * (1.0f / 64.0f);
            float d0 = x0 - mean, d1 = x1 - mean;
            float vs = d0*d0 + d1*d1;
#pragma unroll
            for (int off = 16; off > 0; off >>= 1) vs += __shfl_xor_sync(0xffffffffu, vs, off);
            if (lane == 0) {
                scal[1] = mean;
                scal[2] = 1.0f / sqrtf(vs * (1.0f / 64.0f) + 1e-5f);
            }
        }
        __syncthreads();
        if (tid < 64) hist[tid] = (tmp[tid] - scal[1]) * scal[2];
        __syncthreads();

        // ---- c = concat(ctx, hist) @ Wc + bc  (UNNORMALIZED in smem)
        {
            float s = 0.0f;
#pragma unroll
            for (int i = 0; i < 24; i++) {
                int gi = irow + i;
                float x = (gi < 128) ? ctxs[gi] : hist[gi - 128];
                s = fmaf(x, wreg[i], s);
            }
            cpart[(tid >> 6) * 64 + col] = s;
        }
        __syncthreads();
        if (tid < 64) {
            float s = bcs[tid];
#pragma unroll
            for (int p = 0; p < 8; p++) s += cpart[p*64 + tid];
            cvec[tid] = s;
        }
        __syncthreads();

        // ---- per-warp redundant norm (bitwise identical everywhere);
        //      normalization folded into the exp argument below.
        float invc;
        {
            float c0 = cvec[lane], c1 = cvec[lane + 32];
            float ssn = c0*c0 + c1*c1;
#pragma unroll
            for (int off = 16; off > 0; off >>= 1)
                ssn += __shfl_xor_sync(0xffffffffu, ssn, off);
            invc = 1.0f / fmaxf(sqrtf(ssn), 1e-12f);
        }

        // ---- raw scores s = emb@c ; e = exp(s*invc)
        float sx = 0.f, sy = 0.f;
        if (tid < NCACHE / 2) {
            const float* ep = embc + 2 * tid;
#pragma unroll 8
            for (int k = 0; k < 64; k++) {
                float2 v = *reinterpret_cast<const float2*>(ep + k * NCACHE);
                float ck = cvec[k];
                sx = fmaf(v.x, ck, sx); sy = fmaf(v.y, ck, sy);
            }
        } else {
            const float* ep = embT + rank * RPC + 2 * tid;
#pragma unroll 16
            for (int k = 0; k < 64; k++) {
                float2 v = *reinterpret_cast<const float2*>(ep + (size_t)k * NRc);
                float ck = cvec[k];
                sx = fmaf(v.x, ck, sx); sy = fmaf(v.y, ck, sy);
            }
        }
        float e0 = expf(sx * invc), e1 = expf(sy * invc);
        float t2 = e0 + e1;

        float incl = t2;
#pragma unroll
        for (int off = 1; off < 32; off <<= 1) {
            float n = __shfl_up_sync(0xffffffffu, incl, off);
            if (lane >= off) incl += n;
        }
        if (lane == 31) wred[wid] = incl;
        __syncthreads();
        if (tid == 0) {
            float s = 0.0f;
#pragma unroll
            for (int w = 0; w < 16; w++) { float v = wred[w]; wexc[w] = s; s += v; }
            scal[4] = s;
        }
        __syncthreads();
        float S_local  = scal[4];
        float excl_thr = wexc[wid] + (incl - t2);

        if (tid < CL) st_async_b32(slotS, mbarS_a, (uint32_t)tid, __float_as_uint(S_local));
        mbar_wait_cluster(mbarS_a, par);
        float S_tot = 0.0f, pre = 0.0f;
#pragma unroll
        for (int r = 0; r < CL; r++) {
            float v = exchS[(step & 1) * 4 + r];
            if (r < rank) pre += v;
            S_tot += v;
        }

        float T = rand_vals[b * Ac + step] * S_tot;
        float base = pre + excl_thr;
        int cand = 0x7fffffff;
        int gr = rank * RPC + tid * 2;
        if      (base + e0 > T) cand = gr;
        else if (base + t2 > T) cand = gr + 1;
        if (cand != 0x7fffffff) atomicMin(seli, cand);
        __syncthreads();
        int lc = seli[0];
        if (tid < CL) st_async_b32(slotC, mbarC_a, (uint32_t)tid, (uint32_t)lc);
        mbar_wait_cluster(mbarC_a, par);
        int sel = 0x7fffffff;
#pragma unroll
        for (int r = 0; r < CL; r++) sel = min(sel, exchC[(step & 1) * 4 + r]);
        if (sel == 0x7fffffff) sel = 0;

        if (tid < 64) cur[tid] = embT[(size_t)tid * NRc + sel];
        __syncthreads();
        if (wid == 0) {
            // d_raw = cur . c_unnorm ; score = d_raw * invc
            float d = cur[lane] * cvec[lane] + cur[lane + 32] * cvec[lane + 32];
#pragma unroll
            for (int off = 16; off > 0; off >>= 1) d += __shfl_xor_sync(0xffffffffu, d, off);
            if (lane == 0) scal[0] += d * invc - logf(S_tot);
        }
        if (rank == 0 && tid == 0) out[b * Ac + step] = (float)sel;
        __syncthreads();
    }

    if (rank == 0 && tid == 0) out[Bc*Ac + b] = scal[0];
    if (rank == 0 && tid < 64) out[Bc*Ac + Bc + b*Hc + tid] = hist[tid];
    CLUSTER_SYNC();
}

// ---------------- launcher ----------------
extern "C" void kernel_launch(void* const* d_in, const int* in_sizes, int n_in,
                              void* d_out, int out_size) {
    const float* roles     = (const float*)d_in[0];
    const float* contexts  = (const float*)d_in[1];
    const float* eps       = (const float*)d_in[2];
    const float* rand_vals = (const float*)d_in[3];
    const float* W1  = (const float*)d_in[5];
    const float* b1  = (const float*)d_in[6];
    const float* W21 = (const float*)d_in[7];
    const float* b21 = (const float*)d_in[8];
    const float* W22 = (const float*)d_in[9];
    const float* b22 = (const float*)d_in[10];
    const float* W3  = (const float*)d_in[11];
    const float* b3  = (const float*)d_in[12];
    const float* W4  = (const float*)d_in[13];
    const float* b4  = (const float*)d_in[14];
    const float* Wc  = (const float*)d_in[15];
    const float* bc  = (const float*)d_in[16];
    const float* init_emb = (const float*)d_in[17];
    float* out = (float*)d_out;

    const int vae_smem  = VAE_SMEM_FLOATS  * (int)sizeof(float);
    const int scan_smem = SCAN_SMEM_FLOATS * (int)sizeof(float);
    cudaFuncSetAttribute(vae_kernel,  cudaFuncAttributeMaxDynamicSharedMemorySize, vae_smem);
    cudaFuncSetAttribute(scan_kernel, cudaFuncAttributeMaxDynamicSharedMemorySize, scan_smem);

    vae_kernel<<<MTOT / 128, 256, vae_smem>>>(roles, eps, W1, b1, W21, b21,
                                              W22, b22, W3, b3, W4, b4);
    scan_kernel<<<Bc * CL, STH, scan_smem>>>(contexts, rand_vals, Wc, bc,
                                             init_emb, out);
}

// round 13
// speedup vs baseline: 1.5277x; 1.0147x over previous
#include <cuda_runtime.h>
#include <math.h>
#include <stdint.h>

// ---------------- problem constants ----------------
#define Bc   32
#define NRc  4096
#define DIN  384
#define DCTX 128
#define Hc   64
#define Ac   16
#define MTOT (Bc * NRc)

#define LOG_VAR2_C  (-4.6051701859880914f)
#define INV_VAR2_C  (100.0f)
#define STD2_C      (0.1f)

// ---------------- device scratch (zero-init at module load; scan re-zeros
// g_mse/g_kld at end of every launch so each launch starts from zeros) ----------
__device__ float g_embT[(size_t)Bc * Hc * NRc];   // [b][k][n]
__device__ float g_mse[Bc];
__device__ float g_kld[Bc];

// ---------------- tf32 helpers ----------------
__device__ __forceinline__ float tf32r(float x) {
    uint32_t u; asm("cvt.rna.tf32.f32 %0, %1;" : "=r"(u) : "f"(x));
    return __uint_as_float(u);
}
__device__ __forceinline__ void mma_tf32(float c[4], const uint32_t a[4],
                                         uint32_t b0, uint32_t b1) {
    asm volatile("mma.sync.aligned.m16n8k8.row.col.f32.tf32.tf32.f32 "
        "{%0,%1,%2,%3}, {%4,%5,%6,%7}, {%8,%9}, {%0,%1,%2,%3};"
        : "+f"(c[0]), "+f"(c[1]), "+f"(c[2]), "+f"(c[3])
        : "r"(a[0]), "r"(a[1]), "r"(a[2]), "r"(a[3]), "r"(b0), "r"(b1));
}

#define WSP 68   // conflict-free row stride (floats)

// ---------------- fused VAE kernel ----------------
// + merged W22/W21 dual-accumulator GEMM (shared Hs operand reads)
#define VAE_SMEM_FLOATS (2048 + 1024 + 8320 + 64*WSP + 4096 + 64 + 128)

__global__ __launch_bounds__(256, 2)
void vae_kernel(const float* __restrict__ roles, const float* __restrict__ eps,
                const float* __restrict__ W1,  const float* __restrict__ b1,
                const float* __restrict__ W21, const float* __restrict__ b21,
                const float* __restrict__ W22, const float* __restrict__ b22,
                const float* __restrict__ W3,  const float* __restrict__ b3,
                const float* __restrict__ W4,  const float* __restrict__ b4)
{
    extern __shared__ float sm[];
    float* As  = sm;                 // 16*128
    float* Bs  = As + 2048;          // 16*64
    float* Hs  = Bs + 1024;          // 128*65
    float* Ws  = Hs + 8320;          // 64*WSP  (W22 plain / W3,W4 permuted)
    float* Ws2 = Ws + 64*WSP;        // 64*64   (W21 plain)
    float* red = Ws2 + 4096;         // 64
    float* rns = red + 64;           // 128

    const int tid  = threadIdx.x;
    const int tcol = tid & 15;
    const int trow = tid >> 4;
    const int row0 = blockIdx.x * 128;
    const int b    = row0 >> 12;

    float acc[8][4];

    // ================= GEMM1: h = relu(roles @ W1 + b1)  [fp32, prefetched] =====
#pragma unroll
    for (int i = 0; i < 8; i++)
#pragma unroll
        for (int j = 0; j < 4; j++) acc[i][j] = 0.0f;

    const int am0 = tid >> 2;
    const int ak0 = (tid & 3) * 4;
    const int am1 = (tid + 256) >> 2;
    const int ak1 = ((tid + 256) & 3) * 4;
    const int bk  = tid >> 4;
    const int bj4 = (tid & 15) * 4;

    float4 va0, va1, vb;
    va0 = *reinterpret_cast<const float4*>(roles + (size_t)(row0 + am0) * DIN + ak0);
    va1 = *reinterpret_cast<const float4*>(roles + (size_t)(row0 + am1) * DIN + ak1);
    vb  = *reinterpret_cast<const float4*>(W1 + (size_t)bk * Hc + bj4);

    for (int t = 0; t < 24; t++) {
        As[(ak0 + 0) * 128 + am0] = va0.x;
        As[(ak0 + 1) * 128 + am0] = va0.y;
        As[(ak0 + 2) * 128 + am0] = va0.z;
        As[(ak0 + 3) * 128 + am0] = va0.w;
        As[(ak1 + 0) * 128 + am1] = va1.x;
        As[(ak1 + 1) * 128 + am1] = va1.y;
        As[(ak1 + 2) * 128 + am1] = va1.z;
        As[(ak1 + 3) * 128 + am1] = va1.w;
        *reinterpret_cast<float4*>(&Bs[bk * 64 + bj4]) = vb;
        __syncthreads();

        if (t + 1 < 24) {
            const int kt = (t + 1) * 16;
            va0 = *reinterpret_cast<const float4*>(
                roles + (size_t)(row0 + am0) * DIN + kt + ak0);
            va1 = *reinterpret_cast<const float4*>(
                roles + (size_t)(row0 + am1) * DIN + kt + ak1);
            vb  = *reinterpret_cast<const float4*>(
                W1 + (size_t)(kt + bk) * Hc + bj4);
        }

#pragma unroll
        for (int k = 0; k < 16; k++) {
            float a[8];
            *reinterpret_cast<float4*>(&a[0]) = *reinterpret_cast<float4*>(&As[k*128 + trow*8]);
            *reinterpret_cast<float4*>(&a[4]) = *reinterpret_cast<float4*>(&As[k*128 + trow*8 + 4]);
            float4 bb = *reinterpret_cast<float4*>(&Bs[k*64 + tcol*4]);
#pragma unroll
            for (int i = 0; i < 8; i++) {
                acc[i][0] += a[i] * bb.x;
                acc[i][1] += a[i] * bb.y;
                acc[i][2] += a[i] * bb.z;
                acc[i][3] += a[i] * bb.w;
            }
        }
        __syncthreads();
    }
    {
        float4 bv = *reinterpret_cast<const float4*>(b1 + tcol * 4);
#pragma unroll
        for (int i = 0; i < 8; i++) {
            int r = trow * 8 + i;
            Hs[r*65 + tcol*4 + 0] = fmaxf(acc[i][0] + bv.x, 0.0f);
            Hs[r*65 + tcol*4 + 1] = fmaxf(acc[i][1] + bv.y, 0.0f);
            Hs[r*65 + tcol*4 + 2] = fmaxf(acc[i][2] + bv.z, 0.0f);
            Hs[r*65 + tcol*4 + 3] = fmaxf(acc[i][3] + bv.w, 0.0f);
        }
    }
    // stage BOTH W22 (Ws, plain) and W21 (Ws2, plain)
    for (int t = tid; t < 1024; t += 256) {
        *reinterpret_cast<float4*>(&Ws [t*4]) = *reinterpret_cast<const float4*>(W22 + t*4);
        *reinterpret_cast<float4*>(&Ws2[t*4]) = *reinterpret_cast<const float4*>(W21 + t*4);
    }
    __syncthreads();

    float kacc = 0.0f;

    // ========== MERGED: log_var = h@W22+b22  AND  mu = h@W21+b21  [fp32] ========
    float ac2[8][4];   // log_var accumulators
#pragma unroll
    for (int i = 0; i < 8; i++)
#pragma unroll
        for (int j = 0; j < 4; j++) { acc[i][j] = 0.0f; ac2[i][j] = 0.0f; }
#pragma unroll 4
    for (int k = 0; k < 64; k++) {
        float a[8];
#pragma unroll
        for (int i = 0; i < 8; i++) a[i] = Hs[(trow*8 + i)*65 + k];
        float4 b2 = *reinterpret_cast<float4*>(&Ws [k*64 + tcol*4]);
        float4 b1v = *reinterpret_cast<float4*>(&Ws2[k*64 + tcol*4]);
#pragma unroll
        for (int i = 0; i < 8; i++) {
            ac2[i][0] += a[i]*b2.x;  ac2[i][1] += a[i]*b2.y;
            ac2[i][2] += a[i]*b2.z;  ac2[i][3] += a[i]*b2.w;
            acc[i][0] += a[i]*b1v.x; acc[i][1] += a[i]*b1v.y;
            acc[i][2] += a[i]*b1v.z; acc[i][3] += a[i]*b1v.w;
        }
    }
    // fused epilogue: kld terms + z = mu + eps * exp(0.5 lv) * STD2
    {
        float4 bv22 = *reinterpret_cast<const float4*>(b22 + tcol * 4);
        float4 bv21 = *reinterpret_cast<const float4*>(b21 + tcol * 4);
        float b22a[4] = {bv22.x, bv22.y, bv22.z, bv22.w};
        float b21a[4] = {bv21.x, bv21.y, bv21.z, bv21.w};
#pragma unroll
        for (int i = 0; i < 8; i++) {
            float4 ev = *reinterpret_cast<const float4*>(
                eps + (size_t)(row0 + trow*8 + i) * Hc + tcol * 4);
            float eva[4] = {ev.x, ev.y, ev.z, ev.w};
#pragma unroll
            for (int j = 0; j < 4; j++) {
                float lv = ac2[i][j] + b22a[j];
                float ex = expf(lv);
                kacc += (1.0f - LOG_VAR2_C + lv - ex * INV_VAR2_C);
                float mu = acc[i][j] + b21a[j];
                kacc -= mu * mu * INV_VAR2_C;
                float s  = expf(0.5f * lv) * STD2_C;
                acc[i][j] = mu + eva[j] * s;    // z
            }
        }
    }
    __syncthreads();
    // z (fp32) -> Hs ; stage Ws = permuted tf32(W3)
#pragma unroll
    for (int i = 0; i < 8; i++) {
        int r = trow * 8 + i;
        Hs[r*65 + tcol*4 + 0] = acc[i][0];
        Hs[r*65 + tcol*4 + 1] = acc[i][1];
        Hs[r*65 + tcol*4 + 2] = acc[i][2];
        Hs[r*65 + tcol*4 + 3] = acc[i][3];
    }
    for (int t = tid; t < 4096; t += 256) {
        int k = t >> 6, n = t & 63;
        Ws[k*WSP + ((n & 7) << 3) + (n >> 3)] = tf32r(W3[t]);
    }
    __syncthreads();

    // ================= role_emb = l2norm(z), stored transposed =================
    if (tid < 128) {
        float ss = 0.0f;
#pragma unroll
        for (int k = 0; k < 64; k++) { float v = Hs[tid*65 + k]; ss += v * v; }
        rns[tid] = 1.0f / fmaxf(sqrtf(ss), 1e-12f);
    }
    __syncthreads();
    {
        const int nloc0 = row0 & (NRc - 1);
        for (int t = tid; t < 128 * 64; t += 256) {
            int k = t >> 7;
            int r = t & 127;
            g_embT[((size_t)b * Hc + k) * NRc + nloc0 + r] = Hs[r*65 + k] * rns[r];
        }
    }
    // z rounding happens in fragment build below (no smem pass)

    // ================= tf32 HMMA path: g = relu(z@W3+b3); mse(g@W4+b4) ========
    const int wid  = tid >> 5;
    const int lane = tid & 31;
    const int gid  = lane >> 2;
    const int tig  = lane & 3;
    const int mrow = wid * 16;

    uint32_t afr[8][4];
#pragma unroll
    for (int kt = 0; kt < 8; kt++) {
        int k0 = kt * 8;
        afr[kt][0] = __float_as_uint(tf32r(Hs[(mrow+gid  )*65 + k0+tig  ]));
        afr[kt][1] = __float_as_uint(tf32r(Hs[(mrow+gid+8)*65 + k0+tig  ]));
        afr[kt][2] = __float_as_uint(tf32r(Hs[(mrow+gid  )*65 + k0+tig+4]));
        afr[kt][3] = __float_as_uint(tf32r(Hs[(mrow+gid+8)*65 + k0+tig+4]));
    }
    float cfr[8][4];
#pragma unroll
    for (int nt = 0; nt < 8; nt++)
#pragma unroll
        for (int j = 0; j < 4; j++) cfr[nt][j] = 0.0f;
#pragma unroll
    for (int kt = 0; kt < 8; kt++) {
        const float4* p0 = reinterpret_cast<const float4*>(&Ws[(kt*8+tig  )*WSP + gid*8]);
        const float4* p1 = reinterpret_cast<const float4*>(&Ws[(kt*8+tig+4)*WSP + gid*8]);
        float4 b0a = p0[0], b0b = p0[1];
        float4 b1a = p1[0], b1b = p1[1];
        mma_tf32(cfr[0], afr[kt], __float_as_uint(b0a.x), __float_as_uint(b1a.x));
        mma_tf32(cfr[1], afr[kt], __float_as_uint(b0a.y), __float_as_uint(b1a.y));
        mma_tf32(cfr[2], afr[kt], __float_as_uint(b0a.z), __float_as_uint(b1a.z));
        mma_tf32(cfr[3], afr[kt], __float_as_uint(b0a.w), __float_as_uint(b1a.w));
        mma_tf32(cfr[4], afr[kt], __float_as_uint(b0b.x), __float_as_uint(b1b.x));
        mma_tf32(cfr[5], afr[kt], __float_as_uint(b0b.y), __float_as_uint(b1b.y));
        mma_tf32(cfr[6], afr[kt], __float_as_uint(b0b.z), __float_as_uint(b1b.z));
        mma_tf32(cfr[7], afr[kt], __float_as_uint(b0b.w), __float_as_uint(b1b.w));
    }
    __syncthreads();
#pragma unroll
    for (int nt = 0; nt < 8; nt++) {
        int col = nt*8 + 2*tig;
        float2 b3v = *reinterpret_cast<const float2*>(b3 + col);
        Hs[(mrow+gid  )*65 + col    ] = tf32r(fmaxf(cfr[nt][0] + b3v.x, 0.0f));
        Hs[(mrow+gid  )*65 + col + 1] = tf32r(fmaxf(cfr[nt][1] + b3v.y, 0.0f));
        Hs[(mrow+gid+8)*65 + col    ] = tf32r(fmaxf(cfr[nt][2] + b3v.x, 0.0f));
        Hs[(mrow+gid+8)*65 + col + 1] = tf32r(fmaxf(cfr[nt][3] + b3v.y, 0.0f));
    }
    __syncthreads();
#pragma unroll
    for (int kt = 0; kt < 8; kt++) {
        int k0 = kt * 8;
        afr[kt][0] = __float_as_uint(Hs[(mrow+gid  )*65 + k0+tig  ]);
        afr[kt][1] = __float_as_uint(Hs[(mrow+gid+8)*65 + k0+tig  ]);
        afr[kt][2] = __float_as_uint(Hs[(mrow+gid  )*65 + k0+tig+4]);
        afr[kt][3] = __float_as_uint(Hs[(mrow+gid+8)*65 + k0+tig+4]);
    }

    // W4 chunk staging: thread owns 16 consecutive floats; double-buffered
    const int sk = tid >> 2;
    const int sn = (tid & 3) * 16;
    float4 wpre[4];
#pragma unroll
    for (int q = 0; q < 4; q++)
        wpre[q] = *reinterpret_cast<const float4*>(
            W4 + (size_t)sk * DIN + sn + q * 4);

    float msacc = 0.0f;
    for (int ch = 0; ch < 6; ch++) {
        __syncthreads();
        {
            const float* wf = reinterpret_cast<const float*>(wpre);
#pragma unroll
            for (int j = 0; j < 16; j++) {
                int n = sn + j;
                Ws[sk*WSP + ((n & 7) << 3) + (n >> 3)] = tf32r(wf[j]);
            }
        }
        __syncthreads();
        if (ch + 1 < 6) {
#pragma unroll
            for (int q = 0; q < 4; q++)
                wpre[q] = *reinterpret_cast<const float4*>(
                    W4 + (size_t)sk * DIN + (ch + 1) * 64 + sn + q * 4);
        }
        float cf[8][4];
#pragma unroll
        for (int nt = 0; nt < 8; nt++)
#pragma unroll
            for (int j = 0; j < 4; j++) cf[nt][j] = 0.0f;
#pragma unroll
        for (int kt = 0; kt < 8; kt++) {
            const float4* p0 = reinterpret_cast<const float4*>(&Ws[(kt*8+tig  )*WSP + gid*8]);
            const float4* p1 = reinterpret_cast<const float4*>(&Ws[(kt*8+tig+4)*WSP + gid*8]);
            float4 b0a = p0[0], b0b = p0[1];
            float4 b1a = p1[0], b1b = p1[1];
            mma_tf32(cf[0], afr[kt], __float_as_uint(b0a.x), __float_as_uint(b1a.x));
            mma_tf32(cf[1], afr[kt], __float_as_uint(b0a.y), __float_as_uint(b1a.y));
            mma_tf32(cf[2], afr[kt], __float_as_uint(b0a.z), __float_as_uint(b1a.z));
            mma_tf32(cf[3], afr[kt], __float_as_uint(b0a.w), __float_as_uint(b1a.w));
            mma_tf32(cf[4], afr[kt], __float_as_uint(b0b.x), __float_as_uint(b1b.x));
            mma_tf32(cf[5], afr[kt], __float_as_uint(b0b.y), __float_as_uint(b1b.y));
            mma_tf32(cf[6], afr[kt], __float_as_uint(b0b.z), __float_as_uint(b1b.z));
            mma_tf32(cf[7], afr[kt], __float_as_uint(b0b.w), __float_as_uint(b1b.w));
        }
#pragma unroll
        for (int nt = 0; nt < 8; nt++) {
            int col = ch*64 + nt*8 + 2*tig;
            float2 b4v = *reinterpret_cast<const float2*>(b4 + col);
            float2 r0v = *reinterpret_cast<const float2*>(
                roles + (size_t)(row0 + mrow + gid    ) * DIN + col);
            float2 r1v = *reinterpret_cast<const float2*>(
                roles + (size_t)(row0 + mrow + gid + 8) * DIN + col);
            float d;
            d = cf[nt][0] + b4v.x - r0v.x; msacc += d*d;
            d = cf[nt][1] + b4v.y - r0v.y; msacc += d*d;
            d = cf[nt][2] + b4v.x - r1v.x; msacc += d*d;
            d = cf[nt][3] + b4v.y - r1v.y; msacc += d*d;
        }
    }

    // ================= block reduce kld / mse =================
    float ks = kacc, ms = msacc;
#pragma unroll
    for (int off = 16; off > 0; off >>= 1) {
        ks += __shfl_xor_sync(0xffffffffu, ks, off);
        ms += __shfl_xor_sync(0xffffffffu, ms, off);
    }
    __syncthreads();
    if ((tid & 31) == 0) { red[tid >> 5] = ks; red[8 + (tid >> 5)] = ms; }
    __syncthreads();
    if (tid == 0) {
        float kt = 0.0f, mt = 0.0f;
#pragma unroll
        for (int w = 0; w < 8; w++) { kt += red[w]; mt += red[8 + w]; }
        atomicAdd(&g_kld[b], kt);
        atomicAdd(&g_mse[b], mt);
    }
}

// ---------------- cluster / mbarrier helpers ----------------
__device__ __forceinline__ uint32_t s2u(const void* p) {
    uint32_t a;
    asm("{ .reg .u64 t; cvta.to.shared.u64 t, %1; cvt.u32.u64 %0, t; }" : "=r"(a) : "l"(p));
    return a;
}
__device__ __forceinline__ void mbar_init(uint32_t mbar, uint32_t cnt) {
    asm volatile("mbarrier.init.shared.b64 [%0], %1;" :: "r"(mbar), "r"(cnt) : "memory");
}
__device__ __forceinline__ void mbar_expect_tx(uint32_t mbar, uint32_t bytes) {
    asm volatile("mbarrier.arrive.expect_tx.shared.b64 _, [%0], %1;"
                 :: "r"(mbar), "r"(bytes) : "memory");
}
__device__ __forceinline__ void st_async_b32(uint32_t slot, uint32_t mbar,
                                             uint32_t peer, uint32_t val) {
    uint32_t rs, rb;
    asm("mapa.shared::cluster.u32 %0, %1, %2;" : "=r"(rs) : "r"(slot), "r"(peer));
    asm("mapa.shared::cluster.u32 %0, %1, %2;" : "=r"(rb) : "r"(mbar), "r"(peer));
    asm volatile("st.async.shared::cluster.mbarrier::complete_tx::bytes.b32 [%0], %1, [%2];"
                 :: "r"(rs), "r"(val), "r"(rb) : "memory");
}
__device__ __forceinline__ void mbar_wait_cluster(uint32_t mbar, uint32_t parity) {
    uint32_t done;
    asm volatile("{\n\t.reg .pred p;\n\t"
        "mbarrier.try_wait.parity.acquire.cluster.shared::cta.b64 p, [%1], %2;\n\t"
        "selp.b32 %0, 1, 0, p;\n\t}"
        : "=r"(done) : "r"(mbar), "r"(parity) : "memory");
    while (!done) {
        asm volatile("{\n\t.reg .pred p;\n\t"
            "mbarrier.try_wait.parity.acquire.cluster.shared::cta.b64 p, [%1], %2, 0x989680;\n\t"
            "selp.b32 %0, 1, 0, p;\n\t}"
            : "=r"(done) : "r"(mbar), "r"(parity) : "memory");
    }
}
#define CLUSTER_SYNC() do { \
    asm volatile("barrier.cluster.arrive.aligned;" ::: "memory"); \
    asm volatile("barrier.cluster.wait.aligned;"   ::: "memory"); } while (0)

// ---------------- cluster-parallel selection scan (round-12, frozen) ----------
#define CL 4
#define STH 512
#define RPC (NRc / CL)
#define NCACHE 768
#define SCAN_SMEM_FLOATS (1024 + 64*NCACHE)

__global__ __launch_bounds__(STH, 1) __cluster_dims__(CL, 1, 1)
void scan_kernel(const float* __restrict__ contexts, const float* __restrict__ rand_vals,
                 const float* __restrict__ Wc, const float* __restrict__ bc,
                 const float* __restrict__ init_emb, float* __restrict__ out)
{
    extern __shared__ float sm[];
    unsigned long long* mbar = (unsigned long long*)sm;
    float* exchS = sm + 4;
    int*   exchC = (int*)(sm + 12);
    int*   seli  = (int*)(sm + 20);
    float* scal  = sm + 21;
    float* wred  = sm + 28;
    float* wexc  = sm + 44;
    float* ctxs  = sm + 60;
    float* bcs   = sm + 188;
    float* hist  = sm + 252;
    float* cur   = sm + 316;
    float* tmp   = sm + 380;
    float* cvec  = sm + 444;
    float* cpart = sm + 508;
    float* embc  = sm + 1024;

    const int b    = blockIdx.x >> 2;
    const int rank = blockIdx.x & 3;
    const int tid  = threadIdx.x;
    const int lane = tid & 31;
    const int wid  = tid >> 5;

    if (blockIdx.x == 0 && tid == 0) {
        float v = 0.0f;
        for (int bb = 0; bb < Bc; bb++) {
            float mse = g_mse[bb] * (1.0f / ((float)NRc * (float)DIN));
            float kld = (-0.5f / ((float)NRc * (float)Hc)) * g_kld[bb];
            v += mse + kld;
        }
        out[Bc*Ac + Bc + Bc*Hc] = v / (float)Bc;
        for (int bb = 0; bb < Bc; bb++) { g_mse[bb] = 0.0f; g_kld[bb] = 0.0f; }
    }

    const uint32_t mbarS_a = s2u(&mbar[0]);
    const uint32_t mbarC_a = s2u(&mbar[1]);

    const float* embT = g_embT + (size_t)b * Hc * NRc;

    const int col  = tid & 63;
    const int irow = (tid >> 6) * 24;
    float wreg[24];
#pragma unroll
    for (int i = 0; i < 24; i++) wreg[i] = Wc[(size_t)(irow + i) * 64 + col];

    for (int t = tid; t < 64 * NCACHE / 4; t += STH) {
        int k  = t / (NCACHE / 4);
        int n4 = (t % (NCACHE / 4)) * 4;
        *reinterpret_cast<float4*>(&embc[k * NCACHE + n4]) =
            *reinterpret_cast<const float4*>(embT + (size_t)k * NRc + rank * RPC + n4);
    }
    if (tid < 128) ctxs[tid] = contexts[b * DCTX + tid];
    if (tid < 64)  { bcs[tid] = bc[tid]; float iv = init_emb[tid]; hist[tid] = iv; cur[tid] = iv; }
    if (tid == 0)  {
        scal[0] = 0.0f;
        mbar_init(mbarS_a, 1);
        mbar_init(mbarC_a, 1);
    }
    __syncthreads();
    CLUSTER_SYNC();

    for (int step = 0; step < Ac; step++) {
        const uint32_t par = (uint32_t)(step & 1);
        const uint32_t slotS = s2u(&exchS[(step & 1) * 4 + rank]);
        const uint32_t slotC = s2u(&exchC[(step & 1) * 4 + rank]);

        if (tid == 0) {
            mbar_expect_tx(mbarS_a, 16);
            mbar_expect_tx(mbarC_a, 16);
            seli[0] = 0x7fffffff;
        }
        if (tid < 64) tmp[tid] = hist[tid] + cur[tid];
        __syncthreads();
        if (wid == 0) {
            float x0 = tmp[lane], x1 = tmp[lane + 32];
            float s = x0 + x1;
#pragma unroll
            for (int off = 16; off > 0; off >>= 1) s += __shfl_xor_sync(0xffffffffu, s, off);
            float mean = s * (1.0f / 64.0f);
            float d0 = x0 - mean, d1 = x1 - mean;
            float vs = d0*d0 + d1*d1;
#pragma unroll
            for (int off = 16; off > 0; off >>= 1) vs += __shfl_xor_sync(0xffffffffu, vs, off);
            if (lane == 0) {
                scal[1] = mean;
                scal[2] = 1.0f / sqrtf(vs * (1.0f / 64.0f) + 1e-5f);
            }
        }
        __syncthreads();
        if (tid < 64) hist[tid] = (tmp[tid] - scal[1]) * scal[2];
        __syncthreads();

        {
            float s = 0.0f;
#pragma unroll
            for (int i = 0; i < 24; i++) {
                int gi = irow + i;
                float x = (gi < 128) ? ctxs[gi] : hist[gi - 128];
                s = fmaf(x, wreg[i], s);
            }
            cpart[(tid >> 6) * 64 + col] = s;
        }
        __syncthreads();
        if (tid < 64) {
            float s = bcs[tid];
#pragma unroll
            for (int p = 0; p < 8; p++) s += cpart[p*64 + tid];
            cvec[tid] = s;
        }
        __syncthreads();

        float invc;
        {
            float c0 = cvec[lane], c1 = cvec[lane + 32];
            float ssn = c0*c0 + c1*c1;
#pragma unroll
            for (int off = 16; off > 0; off >>= 1)
                ssn += __shfl_xor_sync(0xffffffffu, ssn, off);
            invc = 1.0f / fmaxf(sqrtf(ssn), 1e-12f);
        }

        float sx = 0.f, sy = 0.f;
        if (tid < NCACHE / 2) {
            const float* ep = embc + 2 * tid;
#pragma unroll 8
            for (int k = 0; k < 64; k++) {
                float2 v = *reinterpret_cast<const float2*>(ep + k * NCACHE);
                float ck = cvec[k];
                sx = fmaf(v.x, ck, sx); sy = fmaf(v.y, ck, sy);
            }
        } else {
            const float* ep = embT + rank * RPC + 2 * tid;
#pragma unroll 16
            for (int k = 0; k < 64; k++) {
                float2 v = *reinterpret_cast<const float2*>(ep + (size_t)k * NRc);
                float ck = cvec[k];
                sx = fmaf(v.x, ck, sx); sy = fmaf(v.y, ck, sy);
            }
        }
        float e0 = expf(sx * invc), e1 = expf(sy * invc);
        float t2 = e0 + e1;

        float incl = t2;
#pragma unroll
        for (int off = 1; off < 32; off <<= 1) {
            float n = __shfl_up_sync(0xffffffffu, incl, off);
            if (lane >= off) incl += n;
        }
        if (lane == 31) wred[wid] = incl;
        __syncthreads();
        if (tid == 0) {
            float s = 0.0f;
#pragma unroll
            for (int w = 0; w < 16; w++) { float v = wred[w]; wexc[w] = s; s += v; }
            scal[4] = s;
        }
        __syncthreads();
        float S_local  = scal[4];
        float excl_thr = wexc[wid] + (incl - t2);

        if (tid < CL) st_async_b32(slotS, mbarS_a, (uint32_t)tid, __float_as_uint(S_local));
        mbar_wait_cluster(mbarS_a, par);
        float S_tot = 0.0f, pre = 0.0f;
#pragma unroll
        for (int r = 0; r < CL; r++) {
            float v = exchS[(step & 1) * 4 + r];
            if (r < rank) pre += v;
            S_tot += v;
        }

        float T = rand_vals[b * Ac + step] * S_tot;
        float base = pre + excl_thr;
        int cand = 0x7fffffff;
        int gr = rank * RPC + tid * 2;
        if      (base + e0 > T) cand = gr;
        else if (base + t2 > T) cand = gr + 1;
        if (cand != 0x7fffffff) atomicMin(seli, cand);
        __syncthreads();
        int lc = seli[0];
        if (tid < CL) st_async_b32(slotC, mbarC_a, (uint32_t)tid, (uint32_t)lc);
        mbar_wait_cluster(mbarC_a, par);
        int sel = 0x7fffffff;
#pragma unroll
        for (int r = 0; r < CL; r++) sel = min(sel, exchC[(step & 1) * 4 + r]);
        if (sel == 0x7fffffff) sel = 0;

        if (tid < 64) cur[tid] = embT[(size_t)tid * NRc + sel];
        __syncthreads();
        if (wid == 0) {
            float d = cur[lane] * cvec[lane] + cur[lane + 32] * cvec[lane + 32];
#pragma unroll
            for (int off = 16; off > 0; off >>= 1) d += __shfl_xor_sync(0xffffffffu, d, off);
            if (lane == 0) scal[0] += d * invc - logf(S_tot);
        }
        if (rank == 0 && tid == 0) out[b * Ac + step] = (float)sel;
        __syncthreads();
    }

    if (rank == 0 && tid == 0) out[Bc*Ac + b] = scal[0];
    if (rank == 0 && tid < 64) out[Bc*Ac + Bc + b*Hc + tid] = hist[tid];
    CLUSTER_SYNC();
}

// ---------------- launcher ----------------
extern "C" void kernel_launch(void* const* d_in, const int* in_sizes, int n_in,
                              void* d_out, int out_size) {
    const float* roles     = (const float*)d_in[0];
    const float* contexts  = (const float*)d_in[1];
    const float* eps       = (const float*)d_in[2];
    const float* rand_vals = (const float*)d_in[3];
    const float* W1  = (const float*)d_in[5];
    const float* b1  = (const float*)d_in[6];
    const float* W21 = (const float*)d_in[7];
    const float* b21 = (const float*)d_in[8];
    const float* W22 = (const float*)d_in[9];
    const float* b22 = (const float*)d_in[10];
    const float* W3  = (const float*)d_in[11];
    const float* b3  = (const float*)d_in[12];
    const float* W4  = (const float*)d_in[13];
    const float* b4  = (const float*)d_in[14];
    const float* Wc  = (const float*)d_in[15];
    const float* bc  = (const float*)d_in[16];
    const float* init_emb = (const float*)d_in[17];
    float* out = (float*)d_out;

    const int vae_smem  = VAE_SMEM_FLOATS  * (int)sizeof(float);
    const int scan_smem = SCAN_SMEM_FLOATS * (int)sizeof(float);
    cudaFuncSetAttribute(vae_kernel,  cudaFuncAttributeMaxDynamicSharedMemorySize, vae_smem);
    cudaFuncSetAttribute(scan_kernel, cudaFuncAttributeMaxDynamicSharedMemorySize, scan_smem);

    vae_kernel<<<MTOT / 128, 256, vae_smem>>>(roles, eps, W1, b1, W21, b21,
                                              W22, b22, W3, b3, W4, b4);
    scan_kernel<<<Bc * CL, STH, scan_smem>>>(contexts, rand_vals, Wc, bc,
                                             init_emb, out);
}